// round 7
// baseline (speedup 1.0000x reference)
#include <cuda_runtime.h>
#include <cstdint>

// ---------------------------------------------------------------------------
// SchNet fused kernel, round 7: HMMA tf32, 256 threads, 1-atom tiles,
// 110.6KB SMEM -> 2 CTAs per SM for latency hiding.
// ---------------------------------------------------------------------------

typedef unsigned long long u64;
typedef unsigned int u32;

#define LDA 72   // A-tile / Wt / Xl row stride (floats)
#define LDX 68   // X / vs / tmpV stride (scalar path)

// float offsets
#define OFF_POS   0        // 192 (pad 256)
#define OFF_BIAS  256      // 128: bf1[64], bf2[64]
#define OFF_XL    384      // 64*72 = 4608
#define OFF_X     4992     // 64*68 = 4352
#define OFF_VS    9344     // 4352
#define OFF_WT1   13696    // 64*72 = 4608 (also Wv1 packed scratch)
#define OFF_WT2   18304    // 4608 (also Wv2 packed scratch)
#define OFF_A     22912    // 64*72 = 4608 (also Wx scratch / tmpV / head scratch)
#define OFF_RED   27520    // 128
#define SMEM_FLOATS 27648
#define SMEM_BYTES  (SMEM_FLOATS * 4)   // 110592 -> 2 CTAs/SM

__device__ __forceinline__ float fast_tanh(float x) {
    float e = __expf(2.0f * x);
    return 1.0f - __fdividef(2.0f, e + 1.0f);
}
// two tanh sharing one rcp: 3 MUFU per pair
__device__ __forceinline__ float2 tanh2(float a, float b) {
    float ya = fminf(a * 2.885390082f, 57.7f);
    float yb = fminf(b * 2.885390082f, 57.7f);
    float ta, tb, rp;
    asm("ex2.approx.f32 %0, %1;" : "=f"(ta) : "f"(ya));
    asm("ex2.approx.f32 %0, %1;" : "=f"(tb) : "f"(yb));
    float pa = ta + 1.0f, pb = tb + 1.0f;
    asm("rcp.approx.f32 %0, %1;" : "=f"(rp) : "f"(pa * pb));
    return make_float2(fmaf(-2.0f * pb, rp, 1.0f), fmaf(-2.0f * pa, rp, 1.0f));
}
__device__ __forceinline__ float tf32r(float f) {
    u32 v; asm("cvt.rna.tf32.f32 %0, %1;" : "=r"(v) : "f"(f));
    return __uint_as_float(v);
}
// k-mod-4 interleaved column offset: offs = {0,16,36,52}[k&3]
__device__ __forceinline__ int koffs(int km4) {
    return (km4 & 1) * 16 + (km4 & 2) * 18;
}

// ---------------------------------------------------------------------------
// Warp MMA block: D[2][2][4] = A rows [row0,row0+32) @ Wt 16-col block.
// ---------------------------------------------------------------------------
__device__ __forceinline__ void mma_block32(const float* __restrict__ Ap, int row0,
                                            const float* __restrict__ Wtp,
                                            float (&D)[2][2][4], int g, int tig) {
    const int offt = koffs(tig);
    float Bf[2][16];
#pragma unroll
    for (int nb = 0; nb < 2; nb++) {
        const float* bp = Wtp + (nb * 8 + g) * LDA + offt;
#pragma unroll
        for (int q = 0; q < 4; q++)
            *(float4*)&Bf[nb][4 * q] = *(const float4*)(bp + 4 * q);
    }
#pragma unroll
    for (int mg = 0; mg < 2; mg++) {
#pragma unroll
        for (int nb = 0; nb < 2; nb++)
#pragma unroll
            for (int i = 0; i < 4; i++) D[mg][nb][i] = 0.0f;
        float Aa[16], Ab[16];
        const float* ap = Ap + (row0 + mg * 16 + g) * LDA + offt;
#pragma unroll
        for (int q = 0; q < 4; q++) {
            *(float4*)&Aa[4 * q] = *(const float4*)(ap + 4 * q);
            *(float4*)&Ab[4 * q] = *(const float4*)(ap + 8 * LDA + 4 * q);
        }
#pragma unroll
        for (int s = 0; s < 8; s++) {
            u32 a0 = __float_as_uint(Aa[2 * s]);
            u32 a2 = __float_as_uint(Aa[2 * s + 1]);
            u32 a1 = __float_as_uint(Ab[2 * s]);
            u32 a3 = __float_as_uint(Ab[2 * s + 1]);
#pragma unroll
            for (int nb = 0; nb < 2; nb++) {
                u32 b0 = __float_as_uint(Bf[nb][2 * s]);
                u32 b1 = __float_as_uint(Bf[nb][2 * s + 1]);
                asm("mma.sync.aligned.m16n8k8.row.col.f32.tf32.tf32.f32 "
                    "{%0,%1,%2,%3}, {%4,%5,%6,%7}, {%8,%9}, {%0,%1,%2,%3};"
                    : "+f"(D[mg][nb][0]), "+f"(D[mg][nb][1]),
                      "+f"(D[mg][nb][2]), "+f"(D[mg][nb][3])
                    : "r"(a0), "r"(a1), "r"(a2), "r"(a3), "r"(b0), "r"(b1));
            }
        }
    }
}

// W[k][n] (64x64 row-major, global) -> Wt_perm[n][pos(k)] tf32, stride 72
__device__ __forceinline__ void store_wT(const float* __restrict__ g,
                                         float* __restrict__ s, int tid) {
#pragma unroll
    for (int ii = 0; ii < 16; ii++) {
        int idx = tid + ii * 256;
        int k = idx >> 6, n = idx & 63;
        s[n * LDA + koffs(k & 3) + (k >> 2)] = tf32r(__ldg(g + idx));
    }
}

// ---- scalar FFMA2 machinery for small 64x64 GEMMs (2 rows/thread) ----
__device__ __forceinline__ void ffma2(u64& d, u64 a, u64 b) {
    asm("fma.rn.f32x2 %0, %1, %2, %0;" : "+l"(d) : "l"(a), "l"(b));
}
__device__ __forceinline__ void unpack2(u64 v, float& lo, float& hi) {
    asm("mov.b64 {%0, %1}, %2;" : "=f"(lo), "=f"(hi) : "l"(v));
}
__device__ __forceinline__ void pack_w(const float* __restrict__ g,
                                       float* __restrict__ s, int tid) {
#pragma unroll
    for (int ii = 0; ii < 16; ii++) {
        int idx = tid + ii * 256;
        int k = idx >> 6, c = idx & 63;
        int p = c >> 1, cl = c & 1;
        int pos = (p & ~3) | (((p & 3) + ((p >> 3) & 3)) & 3);
        s[(k >> 1) * 128 + pos * 4 + cl * 2 + (k & 1)] = __ldg(g + idx);
    }
}
template <int EPI>
__device__ __forceinline__ void gemm2(const float* __restrict__ A, int lda,
                                      const float* __restrict__ Wp,
                                      const float* __restrict__ bias,
                                      float* __restrict__ C, int ldc, int tid) {
    const int rg = tid >> 3, cg = tid & 7, c0 = cg << 3, x = (cg >> 1) & 3;
    const int u0 = (4 * cg + ((0 + x) & 3)) << 2;
    const int u1 = (4 * cg + ((1 + x) & 3)) << 2;
    const int u2 = (4 * cg + ((2 + x) & 3)) << 2;
    const int u3 = (4 * cg + ((3 + x) & 3)) << 2;
    const float* arow0 = A + rg * lda;
    const float* arow1 = arow0 + 32 * lda;
    u64 acc[2][8];
#pragma unroll
    for (int r = 0; r < 2; r++)
#pragma unroll
        for (int c = 0; c < 8; c++) acc[r][c] = 0ULL;
    const float* wk = Wp;
#pragma unroll 8
    for (int k2 = 0; k2 < 32; k2++) {
        ulonglong2 v0 = *(const ulonglong2*)(wk + u0);
        ulonglong2 v1 = *(const ulonglong2*)(wk + u1);
        ulonglong2 v2 = *(const ulonglong2*)(wk + u2);
        ulonglong2 v3 = *(const ulonglong2*)(wk + u3);
        u64 av0 = *(const u64*)(arow0 + 2 * k2);
        u64 av1 = *(const u64*)(arow1 + 2 * k2);
        ffma2(acc[0][0], av0, v0.x); ffma2(acc[0][1], av0, v0.y);
        ffma2(acc[0][2], av0, v1.x); ffma2(acc[0][3], av0, v1.y);
        ffma2(acc[0][4], av0, v2.x); ffma2(acc[0][5], av0, v2.y);
        ffma2(acc[0][6], av0, v3.x); ffma2(acc[0][7], av0, v3.y);
        ffma2(acc[1][0], av1, v0.x); ffma2(acc[1][1], av1, v0.y);
        ffma2(acc[1][2], av1, v1.x); ffma2(acc[1][3], av1, v1.y);
        ffma2(acc[1][4], av1, v2.x); ffma2(acc[1][5], av1, v2.y);
        ffma2(acc[1][6], av1, v3.x); ffma2(acc[1][7], av1, v3.y);
        wk += 128;
    }
    const float4* bp = (const float4*)(bias + c0);
    float4 bA = __ldg(bp), bB = __ldg(bp + 1);
    float b8[8] = {bA.x, bA.y, bA.z, bA.w, bB.x, bB.y, bB.z, bB.w};
#pragma unroll
    for (int r = 0; r < 2; r++) {
        float* cp = C + (rg + 32 * r) * ldc + c0;
        float o[8];
#pragma unroll
        for (int c = 0; c < 8; c++) {
            float lo, hi; unpack2(acc[r][c], lo, hi);
            float v = lo + hi + b8[c];
            if (EPI == 1) v = fast_tanh(v);
            o[c] = v;
        }
        if (EPI == 2) {
            float4 e0 = *(float4*)cp, e1 = *(float4*)(cp + 4);
            o[0] += e0.x; o[1] += e0.y; o[2] += e0.z; o[3] += e0.w;
            o[4] += e1.x; o[5] += e1.y; o[6] += e1.z; o[7] += e1.w;
        }
        *(float4*)cp       = make_float4(o[0], o[1], o[2], o[3]);
        *(float4*)(cp + 4) = make_float4(o[4], o[5], o[6], o[7]);
    }
}

__global__ void __launch_bounds__(256, 2)
schnet_kernel(const float* __restrict__ r_g, const float* __restrict__ v1_g,
              const float* __restrict__ v2_g, const float* __restrict__ cen_g,
              const float* __restrict__ Wx_g,  const float* __restrict__ bx_g,
              const float* __restrict__ Wf1_g, const float* __restrict__ bf1_g,
              const float* __restrict__ Wf2_g, const float* __restrict__ bf2_g,
              const float* __restrict__ Wv1_g, const float* __restrict__ bv1_g,
              const float* __restrict__ Wv2_g, const float* __restrict__ bv2_g,
              const float* __restrict__ W1_g,  const float* __restrict__ b1_g,
              const float* __restrict__ W2_g,  const float* __restrict__ b2_g,
              float* __restrict__ out_g) {
    extern __shared__ float sm[];
    float* pos    = sm + OFF_POS;
    float* bias_s = sm + OFF_BIAS;
    float* Xl     = sm + OFF_XL;
    float* X      = sm + OFF_X;
    float* vs     = sm + OFF_VS;
    float* Wt1    = sm + OFF_WT1;
    float* Wt2    = sm + OFF_WT2;
    float* Ap     = sm + OFF_A;
    float* red    = sm + OFF_RED;

    const int tid  = threadIdx.x, b = blockIdx.x;
    const int wid  = tid >> 5, lane = tid & 31;
    const int rh   = wid >> 2, cb = wid & 3;     // row-half, col-block
    const int g    = lane >> 2, tig = lane & 3;

    // ---- init ----
    if (tid < 192) pos[tid] = r_g[b * 192 + tid];
#pragma unroll
    for (int ii = 0; ii < 16; ii++) {
        int idx = tid + ii * 256;
        int a = idx >> 6, f = idx & 63;
        X[a * LDX + f] = (a < 2) ? __ldg(v1_g + f) : __ldg(v2_g + f);
    }
    __syncthreads();

    float D[2][2][4];

    for (int t = 0; t < 3; t++) {
        const int wofs = t * 4096, bofs = t * 64;

        // stage: Wx packed -> A region; Wf1/Wf2 tf32 perm; biases
        pack_w(Wx_g + wofs, Ap, tid);
        store_wT(Wf1_g + wofs, Wt1, tid);
        store_wT(Wf2_g + wofs, Wt2, tid);
        if (tid < 64) {
            bias_s[tid]      = __ldg(bf1_g + bofs + tid);
            bias_s[64 + tid] = __ldg(bf2_g + bofs + tid);
        }
        __syncthreads();
        gemm2<0>(X, LDX, Ap, bx_g + bofs, Xl, LDA, tid);  // Xl = X@Wx+bx
        __syncthreads();

        const float* Wt1w = Wt1 + cb * 16 * LDA;
        const float* Wt2w = Wt2 + cb * 16 * LDA;

        // ---- 64 tiles x 1 atom ----
        for (int ia = 0; ia < 64; ia++) {
            // rbf fill: thread covers row m, k-range [16*q4, 16*q4+16)
            {
                int m = tid >> 2, q4 = tid & 3;
                float* arow = Ap + m * LDA;
                if (m < 63) {
                    int j = m + (m >= ia);
                    float dx = pos[3 * ia + 0] - pos[3 * j + 0];
                    float dy = pos[3 * ia + 1] - pos[3 * j + 1];
                    float dz = pos[3 * ia + 2] - pos[3 * j + 2];
                    float dd = sqrtf(fmaf(dx, dx, fmaf(dy, dy, dz * dz)));
#pragma unroll
                    for (int h = 0; h < 4; h++) {
                        float* grp = arow + koffs(h) + q4 * 4;
                        float k0 = (float)(16 * q4 + h);
                        float u0 = dd - (k0 + 0.0f) * 0.15625f;
                        float u1 = dd - (k0 + 4.0f) * 0.15625f;
                        float u2 = dd - (k0 + 8.0f) * 0.15625f;
                        float u3 = dd - (k0 + 12.0f) * 0.15625f;
                        float4 v;
                        v.x = tf32r(__expf(-10.0f * u0 * u0));
                        v.y = tf32r(__expf(-10.0f * u1 * u1));
                        v.z = tf32r(__expf(-10.0f * u2 * u2));
                        v.w = tf32r(__expf(-10.0f * u3 * u3));
                        *(float4*)grp = v;
                    }
                } else {
                    float4 z = make_float4(0.f, 0.f, 0.f, 0.f);
#pragma unroll
                    for (int h = 0; h < 4; h++)
                        *(float4*)(arow + koffs(h) + q4 * 4) = z;
                }
            }
            __syncthreads();

            // GEMM1: D = rbf @ Wf1^T
            mma_block32(Ap, rh * 32, Wt1w, D, g, tig);
            __syncthreads();   // all A reads done before epi1 overwrites

            // epilogue1: h1 = tanh(D + bf1) -> A (perm, tf32)
            {
                const int idxb = cb * 4 + (tig >> 1);
                const int p0 = (tig & 1) * 36;
#pragma unroll
                for (int nb = 0; nb < 2; nb++) {
                    float2 bb = *(float2*)&bias_s[cb * 16 + nb * 8 + 2 * tig];
                    int pa = p0 + idxb + 2 * nb;
#pragma unroll
                    for (int mg = 0; mg < 2; mg++) {
                        float* r0p = Ap + (rh * 32 + mg * 16 + g) * LDA;
                        float* r1p = r0p + 8 * LDA;
                        float2 t01 = tanh2(D[mg][nb][0] + bb.x, D[mg][nb][1] + bb.y);
                        float2 t23 = tanh2(D[mg][nb][2] + bb.x, D[mg][nb][3] + bb.y);
                        r0p[pa]      = tf32r(t01.x);
                        r0p[pa + 16] = tf32r(t01.y);
                        r1p[pa]      = tf32r(t23.x);
                        r1p[pa + 16] = tf32r(t23.y);
                    }
                }
            }
            __syncthreads();

            // GEMM2: D = h1 @ Wf2^T
            mma_block32(Ap, rh * 32, Wt2w, D, g, tig);
            __syncthreads();   // A reads done; next fill may overwrite

            // epilogue2: h2 = tanh(D + bf2); cfconv partials -> red
            {
                float2 bb0 = *(float2*)&bias_s[64 + cb * 16 + 2 * tig];
                float2 bb1 = *(float2*)&bias_s[64 + cb * 16 + 8 + 2 * tig];
                float a00 = 0.f, a01 = 0.f, a10 = 0.f, a11 = 0.f;
#pragma unroll
                for (int mg = 0; mg < 2; mg++) {
#pragma unroll
                    for (int rs = 0; rs < 2; rs++) {
                        int m = rh * 32 + mg * 16 + g + 8 * rs;
                        int j = m + (m >= ia);
                        float2 xl0, xl1;
                        if (m != 63) {
                            xl0 = *(float2*)&Xl[j * LDA + cb * 16 + 2 * tig];
                            xl1 = *(float2*)&Xl[j * LDA + cb * 16 + 8 + 2 * tig];
                        } else {
                            xl0 = make_float2(0.f, 0.f);
                            xl1 = make_float2(0.f, 0.f);
                        }
                        float2 t0 = tanh2(D[mg][0][2 * rs] + bb0.x,
                                          D[mg][0][2 * rs + 1] + bb0.y);
                        float2 t1 = tanh2(D[mg][1][2 * rs] + bb1.x,
                                          D[mg][1][2 * rs + 1] + bb1.y);
                        a00 = fmaf(t0.x, xl0.x, a00);
                        a01 = fmaf(t0.y, xl0.y, a01);
                        a10 = fmaf(t1.x, xl1.x, a10);
                        a11 = fmaf(t1.y, xl1.y, a11);
                    }
                }
#pragma unroll
                for (int mk = 4; mk <= 16; mk <<= 1) {
                    a00 += __shfl_xor_sync(0xffffffffu, a00, mk);
                    a01 += __shfl_xor_sync(0xffffffffu, a01, mk);
                    a10 += __shfl_xor_sync(0xffffffffu, a10, mk);
                    a11 += __shfl_xor_sync(0xffffffffu, a11, mk);
                }
                if (g == 0) {
                    *(float2*)&red[rh * 64 + cb * 16 + 2 * tig] =
                        make_float2(a00, a01);
                    *(float2*)&red[rh * 64 + cb * 16 + 8 + 2 * tig] =
                        make_float2(a10, a11);
                }
            }
            __syncthreads();
            if (tid < 64)
                vs[ia * LDX + tid] = red[tid] + red[64 + tid];
            // no extra barrier: next fill writes A only; red rewritten after
            // 4 barriers; vs read only after the loop's __syncthreads.
        }
        __syncthreads();

        // v = tanh(vs@Wv1+b); X += v@Wv2+b  (Wt regions as packed scratch,
        // A region as tmpV)
        pack_w(Wv1_g + wofs, Wt1, tid);
        pack_w(Wv2_g + wofs, Wt2, tid);
        __syncthreads();
        gemm2<1>(vs, LDX, Wt1, bv1_g + bofs, Ap, LDX, tid);
        __syncthreads();
        gemm2<2>(Ap, LDX, Wt2, bv2_g + bofs, X, LDX, tid);
        __syncthreads();
    }

    // ---- output head ----
    {
        float* Wah  = Wt1;            // 2048
        float* Wbh  = Wt2;            // 96
        float* redh = red;
#pragma unroll
        for (int ii = 0; ii < 8; ii++)
            Wah[tid + 256 * ii] = __ldg(W1_g + tid + 256 * ii);
        if (tid < 32) {
            Wbh[tid]      = __ldg(W2_g + tid);
            Wbh[32 + tid] = __ldg(b1_g + tid);
        }
        if (tid == 0) Wbh[64] = __ldg(b2_g);
        __syncthreads();

        int a = tid >> 2, cq = (tid & 3) * 8;
        float acc[8];
#pragma unroll
        for (int j = 0; j < 8; j++) acc[j] = Wbh[32 + cq + j];
#pragma unroll 8
        for (int k = 0; k < 64; k++) {
            float xa = X[a * LDX + k];
            const float* wr = Wah + k * 32 + cq;
#pragma unroll
            for (int j = 0; j < 8; j++) acc[j] = fmaf(xa, wr[j], acc[j]);
        }
        float s = 0.0f;
#pragma unroll
        for (int j = 0; j < 8; j++) s = fmaf(fast_tanh(acc[j]), Wbh[cq + j], s);
#pragma unroll
        for (int off = 16; off > 0; off >>= 1)
            s += __shfl_xor_sync(0xffffffffu, s, off);
        if (lane == 0) redh[wid] = s;
        __syncthreads();
        if (tid == 0) {
            float tot = 0.0f;
#pragma unroll
            for (int w = 0; w < 8; w++) tot += redh[w];
            out_g[b] = tot + 64.0f * Wbh[64];
        }
    }
}

extern "C" void kernel_launch(void* const* d_in, const int* in_sizes, int n_in,
                              void* d_out, int out_size) {
    const float* r_g   = (const float*)d_in[0];
    const float* v1_g  = (const float*)d_in[1];
    const float* v2_g  = (const float*)d_in[2];
    const float* cen_g = (const float*)d_in[3];
    const float* Wx_g  = (const float*)d_in[4];
    const float* bx_g  = (const float*)d_in[5];
    const float* Wf1_g = (const float*)d_in[6];
    const float* bf1_g = (const float*)d_in[7];
    const float* Wf2_g = (const float*)d_in[8];
    const float* bf2_g = (const float*)d_in[9];
    const float* Wv1_g = (const float*)d_in[10];
    const float* bv1_g = (const float*)d_in[11];
    const float* Wv2_g = (const float*)d_in[12];
    const float* bv2_g = (const float*)d_in[13];
    const float* W1_g  = (const float*)d_in[14];
    const float* b1_g  = (const float*)d_in[15];
    const float* W2_g  = (const float*)d_in[16];
    const float* b2_g  = (const float*)d_in[17];
    float* out = (float*)d_out;
    int batch = in_sizes[0] / 192;

    cudaFuncSetAttribute(schnet_kernel,
                         cudaFuncAttributeMaxDynamicSharedMemorySize, SMEM_BYTES);
    schnet_kernel<<<batch, 256, SMEM_BYTES>>>(
        r_g, v1_g, v2_g, cen_g, Wx_g, bx_g, Wf1_g, bf1_g, Wf2_g, bf2_g,
        Wv1_g, bv1_g, Wv2_g, bv2_g, W1_g, b1_g, W2_g, b2_g, out);
}

// round 8
// speedup vs baseline: 1.3662x; 1.3662x over previous
#include <cuda_runtime.h>
#include <cuda_fp16.h>
#include <cstdint>

// ---------------------------------------------------------------------------
// SchNet fused kernel, round 8: warp-owns-rows FA-style fusion.
// Each warp: 16 pair-rows x 64 features. GEMM1 (tf32 m16n8k8) -> tanh ->
// GEMM2 (fp16 m16n8k16) entirely in registers. One named barrier per tile.
// ---------------------------------------------------------------------------

typedef unsigned long long u64;
typedef unsigned int u32;

#define LDA 72   // float stride: A tile, Wt1, Xl
#define LDB2 72  // half stride: Wf2 fp16
#define LDX 68   // X / vs stride (scalar path)

// float offsets
#define OFF_POS   0        // 256
#define OFF_BIAS  256      // 128: bf1[64], bf2[64]
#define OFF_XL    384      // 64*72 = 4608
#define OFF_X     4992     // 4352
#define OFF_VS    9344     // 4352
#define OFF_WT1   13696    // 4608 (tf32 perm Wf1; later Wv1 packed scratch)
#define OFF_W2H   18304    // 2304 (fp16 64x72 halves)
#define OFF_RED   20608    // 2048 (2 bufs x 16 warps x 64)
#define OFF_A     22656    // 256*72 = 18432 (rbf tiles; later scalar scratch)
#define SMEM_FLOATS 41088
#define SMEM_BYTES  (SMEM_FLOATS * 4)   // 164352

#define BAR_RB(id) asm volatile("bar.sync %0, 128;" :: "r"(id) : "memory")

__device__ __forceinline__ float fast_tanh(float x) {
    float e = __expf(2.0f * x);
    return 1.0f - __fdividef(2.0f, e + 1.0f);
}
// two tanh sharing one rcp: 3 MUFU per pair
__device__ __forceinline__ float2 tanh2(float a, float b) {
    float ya = fminf(a * 2.885390082f, 57.7f);
    float yb = fminf(b * 2.885390082f, 57.7f);
    float ta, tb, rp;
    asm("ex2.approx.f32 %0, %1;" : "=f"(ta) : "f"(ya));
    asm("ex2.approx.f32 %0, %1;" : "=f"(tb) : "f"(yb));
    float pa = ta + 1.0f, pb = tb + 1.0f;
    asm("rcp.approx.f32 %0, %1;" : "=f"(rp) : "f"(pa * pb));
    return make_float2(fmaf(-2.0f * pb, rp, 1.0f), fmaf(-2.0f * pa, rp, 1.0f));
}
__device__ __forceinline__ float tf32r(float f) {
    u32 v; asm("cvt.rna.tf32.f32 %0, %1;" : "=r"(v) : "f"(f));
    return __uint_as_float(v);
}
__device__ __forceinline__ u32 packh2(float lo, float hi) {
    __half2 h = __floats2half2_rn(lo, hi);   // .x = lo 16 bits
    return *reinterpret_cast<u32*>(&h);
}
// k-mod-4 interleaved column offset: offs = {0,16,36,52}[k&3]
__device__ __forceinline__ int koffs(int km4) {
    return (km4 & 1) * 16 + (km4 & 2) * 18;
}

__device__ __forceinline__ void mma_tf32(float (&d)[4], u32 a0, u32 a1, u32 a2,
                                         u32 a3, u32 b0, u32 b1) {
    asm("mma.sync.aligned.m16n8k8.row.col.f32.tf32.tf32.f32 "
        "{%0,%1,%2,%3}, {%4,%5,%6,%7}, {%8,%9}, {%0,%1,%2,%3};"
        : "+f"(d[0]), "+f"(d[1]), "+f"(d[2]), "+f"(d[3])
        : "r"(a0), "r"(a1), "r"(a2), "r"(a3), "r"(b0), "r"(b1));
}
__device__ __forceinline__ void mma_f16(float (&d)[4], u32 a0, u32 a1, u32 a2,
                                        u32 a3, u32 b0, u32 b1) {
    asm("mma.sync.aligned.m16n8k16.row.col.f32.f16.f16.f32 "
        "{%0,%1,%2,%3}, {%4,%5,%6,%7}, {%8,%9}, {%0,%1,%2,%3};"
        : "+f"(d[0]), "+f"(d[1]), "+f"(d[2]), "+f"(d[3])
        : "r"(a0), "r"(a1), "r"(a2), "r"(a3), "r"(b0), "r"(b1));
}

// W[k][n] 64x64 row-major global -> WtT_perm[n][pos(k)] tf32, stride LDA
__device__ __forceinline__ void store_wT(const float* __restrict__ g,
                                         float* __restrict__ s, int tid) {
#pragma unroll
    for (int ii = 0; ii < 8; ii++) {
        int idx = tid + ii * 512;
        int k = idx >> 6, n = idx & 63;
        s[n * LDA + koffs(k & 3) + (k >> 2)] = tf32r(__ldg(g + idx));
    }
}
// W[k][n] -> fp16 WT[n][k], stride LDB2 halfs
__device__ __forceinline__ void store_wTh(const float* __restrict__ g,
                                          __half* __restrict__ s, int tid) {
#pragma unroll
    for (int ii = 0; ii < 8; ii++) {
        int idx = tid + ii * 512;
        int k = idx >> 6, n = idx & 63;
        s[n * LDB2 + k] = __float2half(__ldg(g + idx));
    }
}

// ---- scalar FFMA2 machinery for small 64x64 GEMMs (round-6 proven) ----
__device__ __forceinline__ void ffma2(u64& d, u64 a, u64 b) {
    asm("fma.rn.f32x2 %0, %1, %2, %0;" : "+l"(d) : "l"(a), "l"(b));
}
__device__ __forceinline__ void unpack2(u64 v, float& lo, float& hi) {
    asm("mov.b64 {%0, %1}, %2;" : "=f"(lo), "=f"(hi) : "l"(v));
}
__device__ __forceinline__ void pack_w(const float* __restrict__ g,
                                       float* __restrict__ s, int tid) {
#pragma unroll
    for (int ii = 0; ii < 8; ii++) {
        int idx = tid + ii * 512;
        int k = idx >> 6, c = idx & 63;
        int p = c >> 1, cl = c & 1;
        int pos = (p & ~3) | (((p & 3) + ((p >> 3) & 3)) & 3);
        s[(k >> 1) * 128 + pos * 4 + cl * 2 + (k & 1)] = __ldg(g + idx);
    }
}
template <int EPI>
__device__ __forceinline__ void gemm2(const float* __restrict__ A, int lda,
                                      const float* __restrict__ Wp,
                                      const float* __restrict__ bias,
                                      float* __restrict__ C, int ldc, int tid) {
    const int rg = tid >> 3, cg = tid & 7, c0 = cg << 3, x = (cg >> 1) & 3;
    const int u0 = (4 * cg + ((0 + x) & 3)) << 2;
    const int u1 = (4 * cg + ((1 + x) & 3)) << 2;
    const int u2 = (4 * cg + ((2 + x) & 3)) << 2;
    const int u3 = (4 * cg + ((3 + x) & 3)) << 2;
    const float* arow = A + rg * lda;
    u64 acc[8];
#pragma unroll
    for (int c = 0; c < 8; c++) acc[c] = 0ULL;
    const float* wk = Wp;
#pragma unroll 8
    for (int k2 = 0; k2 < 32; k2++) {
        ulonglong2 v0 = *(const ulonglong2*)(wk + u0);
        ulonglong2 v1 = *(const ulonglong2*)(wk + u1);
        ulonglong2 v2 = *(const ulonglong2*)(wk + u2);
        ulonglong2 v3 = *(const ulonglong2*)(wk + u3);
        u64 av = *(const u64*)(arow + 2 * k2);
        ffma2(acc[0], av, v0.x); ffma2(acc[1], av, v0.y);
        ffma2(acc[2], av, v1.x); ffma2(acc[3], av, v1.y);
        ffma2(acc[4], av, v2.x); ffma2(acc[5], av, v2.y);
        ffma2(acc[6], av, v3.x); ffma2(acc[7], av, v3.y);
        wk += 128;
    }
    const float4* bp = (const float4*)(bias + c0);
    float4 bA = __ldg(bp), bB = __ldg(bp + 1);
    float b8[8] = {bA.x, bA.y, bA.z, bA.w, bB.x, bB.y, bB.z, bB.w};
    float* cp = C + rg * ldc + c0;
    float o[8];
#pragma unroll
    for (int c = 0; c < 8; c++) {
        float lo, hi; unpack2(acc[c], lo, hi);
        float v = lo + hi + b8[c];
        if (EPI == 1) v = fast_tanh(v);
        o[c] = v;
    }
    if (EPI == 2) {
        float4 e0 = *(float4*)cp, e1 = *(float4*)(cp + 4);
        o[0] += e0.x; o[1] += e0.y; o[2] += e0.z; o[3] += e0.w;
        o[4] += e1.x; o[5] += e1.y; o[6] += e1.z; o[7] += e1.w;
    }
    *(float4*)cp       = make_float4(o[0], o[1], o[2], o[3]);
    *(float4*)(cp + 4) = make_float4(o[4], o[5], o[6], o[7]);
}

__global__ void __launch_bounds__(512, 1)
schnet_kernel(const float* __restrict__ r_g, const float* __restrict__ v1_g,
              const float* __restrict__ v2_g, const float* __restrict__ cen_g,
              const float* __restrict__ Wx_g,  const float* __restrict__ bx_g,
              const float* __restrict__ Wf1_g, const float* __restrict__ bf1_g,
              const float* __restrict__ Wf2_g, const float* __restrict__ bf2_g,
              const float* __restrict__ Wv1_g, const float* __restrict__ bv1_g,
              const float* __restrict__ Wv2_g, const float* __restrict__ bv2_g,
              const float* __restrict__ W1_g,  const float* __restrict__ b1_g,
              const float* __restrict__ W2_g,  const float* __restrict__ b2_g,
              float* __restrict__ out_g) {
    extern __shared__ float sm[];
    float*  pos    = sm + OFF_POS;
    float*  bias_s = sm + OFF_BIAS;
    float*  Xl     = sm + OFF_XL;
    float*  X      = sm + OFF_X;
    float*  vs     = sm + OFF_VS;
    float*  Wt1    = sm + OFF_WT1;
    __half* Wf2h   = (__half*)(sm + OFF_W2H);
    float*  red    = sm + OFF_RED;
    float*  Ap     = sm + OFF_A;

    const int tid  = threadIdx.x, b = blockIdx.x;
    const int wid  = tid >> 5, lane = tid & 31;
    const int rb   = wid >> 2;            // atom-group (4 warps)
    const int wm   = wid & 3;             // warp-within-atom (row quarter)
    const int g    = lane >> 2, tig = lane & 3;
    const int rb_tid = tid & 127;

    // ---- init ----
    if (tid < 192) pos[tid] = r_g[b * 192 + tid];
#pragma unroll
    for (int ii = 0; ii < 8; ii++) {
        int idx = tid + ii * 512;
        int a = idx >> 6, f = idx & 63;
        X[a * LDX + f] = (a < 2) ? __ldg(v1_g + f) : __ldg(v2_g + f);
    }
    __syncthreads();

    int rbuf = 0;

    for (int t = 0; t < 3; t++) {
        const int wofs = t * 4096, bofs = t * 64;

        // stage weights: Wx packed -> A scratch; Wf1 tf32 perm; Wf2 fp16
        pack_w(Wx_g + wofs, Ap, tid);
        store_wT(Wf1_g + wofs, Wt1, tid);
        store_wTh(Wf2_g + wofs, Wf2h, tid);
        if (tid < 64) {
            bias_s[tid]      = __ldg(bf1_g + bofs + tid);
            bias_s[64 + tid] = __ldg(bf2_g + bofs + tid);
        }
        __syncthreads();
        gemm2<0>(X, LDX, Ap, bx_g + bofs, Xl, LDA, tid);  // Xl = X@Wx+bx
        __syncthreads();

        // ---- 16 tiles x 4 atoms; warp owns rows [16*wid, 16*wid+16) ----
        for (int tt = 0; tt < 16; tt++) {
            const int ia = 4 * tt + rb;

            // fill own 16 rows: lane -> row r=lane>>1, q in {2hf,2hf+1}
            {
                int r = lane >> 1, hf = lane & 1;
                int m = 16 * wm + r;
                float* arow = Ap + (wid * 16 + r) * LDA;
                if (m < 63) {
                    int j = m + (m >= ia);
                    float dx = pos[3 * ia + 0] - pos[3 * j + 0];
                    float dy = pos[3 * ia + 1] - pos[3 * j + 1];
                    float dz = pos[3 * ia + 2] - pos[3 * j + 2];
                    float dd = sqrtf(fmaf(dx, dx, fmaf(dy, dy, dz * dz)));
#pragma unroll
                    for (int qq = 0; qq < 2; qq++) {
                        int q = 2 * hf + qq;
                        float* grp = arow + koffs(q);
                        float c0v = dd - (float)q * 0.15625f;
#pragma unroll
                        for (int i0 = 0; i0 < 16; i0 += 4) {
                            float u0 = c0v - (float)(4 * (i0 + 0)) * 0.15625f;
                            float u1 = c0v - (float)(4 * (i0 + 1)) * 0.15625f;
                            float u2 = c0v - (float)(4 * (i0 + 2)) * 0.15625f;
                            float u3 = c0v - (float)(4 * (i0 + 3)) * 0.15625f;
                            float4 v;
                            v.x = tf32r(__expf(-10.0f * u0 * u0));
                            v.y = tf32r(__expf(-10.0f * u1 * u1));
                            v.z = tf32r(__expf(-10.0f * u2 * u2));
                            v.w = tf32r(__expf(-10.0f * u3 * u3));
                            *(float4*)(grp + i0) = v;
                        }
                    }
                } else {
                    float4 z = make_float4(0.f, 0.f, 0.f, 0.f);
#pragma unroll
                    for (int qq = 0; qq < 2; qq++) {
                        float* grp = arow + koffs(2 * hf + qq);
#pragma unroll
                        for (int i0 = 0; i0 < 16; i0 += 4)
                            *(float4*)(grp + i0) = z;
                    }
                }
            }
            __syncwarp();

            // GEMM1: D1[8][4] = rbf(own 16 rows) @ Wf1^T (all 64 cols)
            float D1[8][4];
            {
                float Aa[16], Ab[16];
                const float* ap = Ap + (wid * 16 + g) * LDA + koffs(tig);
#pragma unroll
                for (int q = 0; q < 4; q++) {
                    *(float4*)&Aa[4 * q] = *(const float4*)(ap + 4 * q);
                    *(float4*)&Ab[4 * q] = *(const float4*)(ap + 8 * LDA + 4 * q);
                }
#pragma unroll
                for (int nb = 0; nb < 8; nb++) {
#pragma unroll
                    for (int i = 0; i < 4; i++) D1[nb][i] = 0.0f;
                    float Bf[16];
                    const float* bp = Wt1 + (nb * 8 + g) * LDA + koffs(tig);
#pragma unroll
                    for (int q = 0; q < 4; q++)
                        *(float4*)&Bf[4 * q] = *(const float4*)(bp + 4 * q);
#pragma unroll
                    for (int s = 0; s < 8; s++)
                        mma_tf32(D1[nb],
                                 __float_as_uint(Aa[2 * s]),
                                 __float_as_uint(Ab[2 * s]),
                                 __float_as_uint(Aa[2 * s + 1]),
                                 __float_as_uint(Ab[2 * s + 1]),
                                 __float_as_uint(Bf[2 * s]),
                                 __float_as_uint(Bf[2 * s + 1]));
                }
            }

            // epi1 in regs: h[nb][0] = rows g, h[nb][1] = rows g+8 (fp16x2)
            u32 h[8][2];
#pragma unroll
            for (int nb = 0; nb < 8; nb++) {
                float bx0 = bias_s[8 * nb + 2 * tig];
                float bx1 = bias_s[8 * nb + 2 * tig + 1];
                float2 t01 = tanh2(D1[nb][0] + bx0, D1[nb][1] + bx1);
                float2 t23 = tanh2(D1[nb][2] + bx0, D1[nb][3] + bx1);
                h[nb][0] = packh2(t01.x, t01.y);
                h[nb][1] = packh2(t23.x, t23.y);
            }

            // GEMM2 (fp16 m16n8k16, A in regs) + epi2 fused per nb2
            const int m_g  = 16 * wm + g;
            const int m_g8 = m_g + 8;
            const int j_g  = m_g + (m_g >= ia);
            const int j_g8 = m_g8 + (m_g8 >= ia);
            const bool pad8 = (m_g8 == 63);
            float pr[8][2];
            const __half* w2base = Wf2h + g * LDB2 + 2 * tig;
#pragma unroll
            for (int nb2 = 0; nb2 < 8; nb2++) {
                float d2[4] = {0.f, 0.f, 0.f, 0.f};
                const __half* w2row = w2base + nb2 * 8 * LDB2;
#pragma unroll
                for (int kb = 0; kb < 4; kb++) {
                    u32 b01 = *(const u32*)(w2row + 16 * kb);
                    u32 b23 = *(const u32*)(w2row + 16 * kb + 8);
                    mma_f16(d2, h[2 * kb][0], h[2 * kb][1],
                            h[2 * kb + 1][0], h[2 * kb + 1][1], b01, b23);
                }
                float bb0 = bias_s[64 + 8 * nb2 + 2 * tig];
                float bb1 = bias_s[64 + 8 * nb2 + 2 * tig + 1];
                float2 tg  = tanh2(d2[0] + bb0, d2[1] + bb1);
                float2 tg8 = tanh2(d2[2] + bb0, d2[3] + bb1);
                float2 xg  = *(const float2*)&Xl[j_g * LDA + 8 * nb2 + 2 * tig];
                float2 xg8 = pad8 ? make_float2(0.f, 0.f)
                             : *(const float2*)&Xl[j_g8 * LDA + 8 * nb2 + 2 * tig];
                pr[nb2][0] = fmaf(tg.x, xg.x, tg8.x * xg8.x);
                pr[nb2][1] = fmaf(tg.y, xg.y, tg8.y * xg8.y);
            }
            // reduce over g (8 lanes share tig)
#pragma unroll
            for (int mk = 4; mk <= 16; mk <<= 1) {
#pragma unroll
                for (int nb2 = 0; nb2 < 8; nb2++) {
                    pr[nb2][0] += __shfl_xor_sync(0xffffffffu, pr[nb2][0], mk);
                    pr[nb2][1] += __shfl_xor_sync(0xffffffffu, pr[nb2][1], mk);
                }
            }
            if (g == 0) {
                float* rp = red + (rbuf * 16 + wid) * 64 + 2 * tig;
#pragma unroll
                for (int nb2 = 0; nb2 < 8; nb2++)
                    *(float2*)(rp + 8 * nb2) = make_float2(pr[nb2][0], pr[nb2][1]);
            }
            BAR_RB(rb + 1);
            if (rb_tid < 64) {
                const float* rp = red + (rbuf * 16 + rb * 4) * 64 + rb_tid;
                vs[ia * LDX + rb_tid] = rp[0] + rp[64] + rp[128] + rp[192];
            }
            rbuf ^= 1;
        }
        __syncthreads();

        // v = tanh(vs@Wv1+b); X += v@Wv2+b (scratch: Wt1 + A region)
        pack_w(Wv1_g + wofs, Wt1, tid);
        pack_w(Wv2_g + wofs, Ap, tid);
        __syncthreads();
        gemm2<1>(vs, LDX, Wt1, bv1_g + bofs, Ap + 8192, LDX, tid);
        __syncthreads();
        gemm2<2>(Ap + 8192, LDX, Ap, bv2_g + bofs, X, LDX, tid);
        __syncthreads();
    }

    // ---- output head ----
    {
        float* Wah  = Ap;
        float* Wbh  = Ap + 2048;
        float* redh = Ap + 4096;
#pragma unroll
        for (int ii = 0; ii < 4; ii++)
            Wah[tid + 512 * ii] = __ldg(W1_g + tid + 512 * ii);
        if (tid < 32) {
            Wbh[tid]      = __ldg(W2_g + tid);
            Wbh[32 + tid] = __ldg(b1_g + tid);
        }
        if (tid == 0) Wbh[64] = __ldg(b2_g);
        __syncthreads();

        int a = tid >> 3, cq = (tid & 7) * 4;
        float acc0 = Wbh[32 + cq + 0], acc1 = Wbh[32 + cq + 1];
        float acc2 = Wbh[32 + cq + 2], acc3 = Wbh[32 + cq + 3];
#pragma unroll 8
        for (int k = 0; k < 64; k++) {
            float xa = X[a * LDX + k];
            const float* wr = Wah + k * 32 + cq;
            acc0 = fmaf(xa, wr[0], acc0);
            acc1 = fmaf(xa, wr[1], acc1);
            acc2 = fmaf(xa, wr[2], acc2);
            acc3 = fmaf(xa, wr[3], acc3);
        }
        float s = fast_tanh(acc0) * Wbh[cq + 0] + fast_tanh(acc1) * Wbh[cq + 1] +
                  fast_tanh(acc2) * Wbh[cq + 2] + fast_tanh(acc3) * Wbh[cq + 3];
#pragma unroll
        for (int off = 16; off > 0; off >>= 1)
            s += __shfl_xor_sync(0xffffffffu, s, off);
        if (lane == 0) redh[wid] = s;
        __syncthreads();
        if (tid == 0) {
            float tot = 0.0f;
#pragma unroll
            for (int w = 0; w < 16; w++) tot += redh[w];
            out_g[b] = tot + 64.0f * Wbh[64];
        }
    }
}

extern "C" void kernel_launch(void* const* d_in, const int* in_sizes, int n_in,
                              void* d_out, int out_size) {
    const float* r_g   = (const float*)d_in[0];
    const float* v1_g  = (const float*)d_in[1];
    const float* v2_g  = (const float*)d_in[2];
    const float* cen_g = (const float*)d_in[3];
    const float* Wx_g  = (const float*)d_in[4];
    const float* bx_g  = (const float*)d_in[5];
    const float* Wf1_g = (const float*)d_in[6];
    const float* bf1_g = (const float*)d_in[7];
    const float* Wf2_g = (const float*)d_in[8];
    const float* bf2_g = (const float*)d_in[9];
    const float* Wv1_g = (const float*)d_in[10];
    const float* bv1_g = (const float*)d_in[11];
    const float* Wv2_g = (const float*)d_in[12];
    const float* bv2_g = (const float*)d_in[13];
    const float* W1_g  = (const float*)d_in[14];
    const float* b1_g  = (const float*)d_in[15];
    const float* W2_g  = (const float*)d_in[16];
    const float* b2_g  = (const float*)d_in[17];
    float* out = (float*)d_out;
    int batch = in_sizes[0] / 192;

    cudaFuncSetAttribute(schnet_kernel,
                         cudaFuncAttributeMaxDynamicSharedMemorySize, SMEM_BYTES);
    schnet_kernel<<<batch, 512, SMEM_BYTES>>>(
        r_g, v1_g, v2_g, cen_g, Wx_g, bx_g, Wf1_g, bf1_g, Wf2_g, bf2_g,
        Wv1_g, bv1_g, Wv2_g, bv2_g, W1_g, b1_g, W2_g, b2_g, out);
}

// round 9
// speedup vs baseline: 1.5392x; 1.1266x over previous
#include <cuda_runtime.h>
#include <cuda_fp16.h>
#include <cstdint>

// ---------------------------------------------------------------------------
// SchNet fused kernel, round 9: rbf computed directly into MMA fragments
// (no A tile in SMEM), fragment-major B layouts for both filter GEMMs,
// epi1 fused into the nb loop (no register spills). 512 thr, 1 CTA/batch.
// ---------------------------------------------------------------------------

typedef unsigned long long u64;
typedef unsigned int u32;

#define LDA 72   // float stride: Xl
#define LDX 68   // X / vs / tmpV stride (scalar path)

// float offsets
#define OFF_POS   0        // 256
#define OFF_BIAS  256      // 128
#define OFF_XL    384      // 64*72 = 4608
#define OFF_X     4992     // 4352
#define OFF_VS    9344     // 4352
#define OFF_B1    13696    // 4096  (frag-major tf32 Wf1; scalar scratch)
#define OFF_B2    17792    // 2048  (frag-major fp16 Wf2; scalar scratch)
#define OFF_RED   19840    // 2048
#define SMEM_FLOATS 21888
#define SMEM_BYTES  (SMEM_FLOATS * 4)   // 87552

#define BAR_RB(id) asm volatile("bar.sync %0, 128;" :: "r"(id) : "memory")

__device__ __forceinline__ float fast_tanh(float x) {
    float e = __expf(2.0f * x);
    return 1.0f - __fdividef(2.0f, e + 1.0f);
}
__device__ __forceinline__ float2 tanh2(float a, float b) {
    float ya = fminf(a * 2.885390082f, 57.7f);
    float yb = fminf(b * 2.885390082f, 57.7f);
    float ta, tb, rp;
    asm("ex2.approx.f32 %0, %1;" : "=f"(ta) : "f"(ya));
    asm("ex2.approx.f32 %0, %1;" : "=f"(tb) : "f"(yb));
    float pa = ta + 1.0f, pb = tb + 1.0f;
    asm("rcp.approx.f32 %0, %1;" : "=f"(rp) : "f"(pa * pb));
    return make_float2(fmaf(-2.0f * pb, rp, 1.0f), fmaf(-2.0f * pa, rp, 1.0f));
}
__device__ __forceinline__ float ex2f(float y) {
    float r; asm("ex2.approx.f32 %0, %1;" : "=f"(r) : "f"(y)); return r;
}
__device__ __forceinline__ float tf32r(float f) {
    u32 v; asm("cvt.rna.tf32.f32 %0, %1;" : "=r"(v) : "f"(f));
    return __uint_as_float(v);
}
__device__ __forceinline__ u32 packh2(float lo, float hi) {
    __half2 h = __floats2half2_rn(lo, hi);
    return *reinterpret_cast<u32*>(&h);
}

__device__ __forceinline__ void mma_tf32(float (&d)[4], float a0, float a1,
                                         float a2, float a3, float b0, float b1) {
    asm("mma.sync.aligned.m16n8k8.row.col.f32.tf32.tf32.f32 "
        "{%0,%1,%2,%3}, {%4,%5,%6,%7}, {%8,%9}, {%0,%1,%2,%3};"
        : "+f"(d[0]), "+f"(d[1]), "+f"(d[2]), "+f"(d[3])
        : "r"(__float_as_uint(a0)), "r"(__float_as_uint(a1)),
          "r"(__float_as_uint(a2)), "r"(__float_as_uint(a3)),
          "r"(__float_as_uint(b0)), "r"(__float_as_uint(b1)));
}
__device__ __forceinline__ void mma_f16(float (&d)[4], u32 a0, u32 a1, u32 a2,
                                        u32 a3, u32 b0, u32 b1) {
    asm("mma.sync.aligned.m16n8k16.row.col.f32.f16.f16.f32 "
        "{%0,%1,%2,%3}, {%4,%5,%6,%7}, {%8,%9}, {%0,%1,%2,%3};"
        : "+f"(d[0]), "+f"(d[1]), "+f"(d[2]), "+f"(d[3])
        : "r"(a0), "r"(a1), "r"(a2), "r"(a3), "r"(b0), "r"(b1));
}

// W[k][n] -> frag-major tf32: lane(4*(n&7)+(k&3)) float fi=k>>2 of block nb=n>>3
__device__ __forceinline__ void stage_b1(const float* __restrict__ g,
                                         float* __restrict__ s, int tid) {
#pragma unroll
    for (int ii = 0; ii < 8; ii++) {
        int idx = tid + ii * 512;
        int k = idx >> 6, n = idx & 63;
        int ln = 4 * (n & 7) + (k & 3);
        int fi = k >> 2;
        s[(((n >> 3) * 4 + (fi >> 2)) * 32 + ln) * 4 + (fi & 3)] = tf32r(__ldg(g + idx));
    }
}
// W[k][n] -> frag-major fp16: lane(4*(n&7)+((k>>1)&3)) u32 i=k>>3, half k&1
__device__ __forceinline__ void stage_b2(const float* __restrict__ g,
                                         __half* __restrict__ s, int tid) {
#pragma unroll
    for (int ii = 0; ii < 8; ii++) {
        int idx = tid + ii * 512;
        int k = idx >> 6, n = idx & 63;
        int ln = 4 * (n & 7) + ((k >> 1) & 3);
        int i = k >> 3;
        s[((((n >> 3) * 2 + (i >> 2)) * 32 + ln) * 4 + (i & 3)) * 2 + (k & 1)] =
            __float2half(__ldg(g + idx));
    }
}

// ---- scalar FFMA2 machinery for small 64x64 GEMMs ----
__device__ __forceinline__ void ffma2(u64& d, u64 a, u64 b) {
    asm("fma.rn.f32x2 %0, %1, %2, %0;" : "+l"(d) : "l"(a), "l"(b));
}
__device__ __forceinline__ void unpack2(u64 v, float& lo, float& hi) {
    asm("mov.b64 {%0, %1}, %2;" : "=f"(lo), "=f"(hi) : "l"(v));
}
__device__ __forceinline__ void pack_w(const float* __restrict__ g,
                                       float* __restrict__ s, int tid) {
#pragma unroll
    for (int ii = 0; ii < 8; ii++) {
        int idx = tid + ii * 512;
        int k = idx >> 6, c = idx & 63;
        int p = c >> 1, cl = c & 1;
        int pos = (p & ~3) | (((p & 3) + ((p >> 3) & 3)) & 3);
        s[(k >> 1) * 128 + pos * 4 + cl * 2 + (k & 1)] = __ldg(g + idx);
    }
}
template <int EPI>
__device__ __forceinline__ void gemm2(const float* __restrict__ A, int lda,
                                      const float* __restrict__ Wp,
                                      const float* __restrict__ bias,
                                      float* __restrict__ C, int ldc, int tid) {
    const int rg = tid >> 3, cg = tid & 7, c0 = cg << 3, x = (cg >> 1) & 3;
    const int u0 = (4 * cg + ((0 + x) & 3)) << 2;
    const int u1 = (4 * cg + ((1 + x) & 3)) << 2;
    const int u2 = (4 * cg + ((2 + x) & 3)) << 2;
    const int u3 = (4 * cg + ((3 + x) & 3)) << 2;
    const float* arow = A + rg * lda;
    u64 acc[8];
#pragma unroll
    for (int c = 0; c < 8; c++) acc[c] = 0ULL;
    const float* wk = Wp;
#pragma unroll 8
    for (int k2 = 0; k2 < 32; k2++) {
        ulonglong2 v0 = *(const ulonglong2*)(wk + u0);
        ulonglong2 v1 = *(const ulonglong2*)(wk + u1);
        ulonglong2 v2 = *(const ulonglong2*)(wk + u2);
        ulonglong2 v3 = *(const ulonglong2*)(wk + u3);
        u64 av = *(const u64*)(arow + 2 * k2);
        ffma2(acc[0], av, v0.x); ffma2(acc[1], av, v0.y);
        ffma2(acc[2], av, v1.x); ffma2(acc[3], av, v1.y);
        ffma2(acc[4], av, v2.x); ffma2(acc[5], av, v2.y);
        ffma2(acc[6], av, v3.x); ffma2(acc[7], av, v3.y);
        wk += 128;
    }
    const float4* bp = (const float4*)(bias + c0);
    float4 bA = __ldg(bp), bB = __ldg(bp + 1);
    float b8[8] = {bA.x, bA.y, bA.z, bA.w, bB.x, bB.y, bB.z, bB.w};
    float* cp = C + rg * ldc + c0;
    float o[8];
#pragma unroll
    for (int c = 0; c < 8; c++) {
        float lo, hi; unpack2(acc[c], lo, hi);
        float v = lo + hi + b8[c];
        if (EPI == 1) v = fast_tanh(v);
        o[c] = v;
    }
    if (EPI == 2) {
        float4 e0 = *(float4*)cp, e1 = *(float4*)(cp + 4);
        o[0] += e0.x; o[1] += e0.y; o[2] += e0.z; o[3] += e0.w;
        o[4] += e1.x; o[5] += e1.y; o[6] += e1.z; o[7] += e1.w;
    }
    *(float4*)cp       = make_float4(o[0], o[1], o[2], o[3]);
    *(float4*)(cp + 4) = make_float4(o[4], o[5], o[6], o[7]);
}

__global__ void __launch_bounds__(512, 1)
schnet_kernel(const float* __restrict__ r_g, const float* __restrict__ v1_g,
              const float* __restrict__ v2_g, const float* __restrict__ cen_g,
              const float* __restrict__ Wx_g,  const float* __restrict__ bx_g,
              const float* __restrict__ Wf1_g, const float* __restrict__ bf1_g,
              const float* __restrict__ Wf2_g, const float* __restrict__ bf2_g,
              const float* __restrict__ Wv1_g, const float* __restrict__ bv1_g,
              const float* __restrict__ Wv2_g, const float* __restrict__ bv2_g,
              const float* __restrict__ W1_g,  const float* __restrict__ b1_g,
              const float* __restrict__ W2_g,  const float* __restrict__ b2_g,
              float* __restrict__ out_g) {
    extern __shared__ float sm[];
    float*  pos    = sm + OFF_POS;
    float*  bias_s = sm + OFF_BIAS;
    float*  Xl     = sm + OFF_XL;
    float*  X      = sm + OFF_X;
    float*  vs     = sm + OFF_VS;
    float*  B1     = sm + OFF_B1;
    __half* B2h    = (__half*)(sm + OFF_B2);
    float*  red    = sm + OFF_RED;

    const int tid  = threadIdx.x, b = blockIdx.x;
    const int wid  = tid >> 5, lane = tid & 31;
    const int rb   = wid >> 2;            // atom-group (4 warps)
    const int wm   = wid & 3;             // warp-within-group
    const int g    = lane >> 2, tig = lane & 3;
    const int rb_tid = tid & 127;

    // ---- init ----
    if (tid < 192) pos[tid] = r_g[b * 192 + tid];
#pragma unroll
    for (int ii = 0; ii < 8; ii++) {
        int idx = tid + ii * 512;
        int a = idx >> 6, f = idx & 63;
        X[a * LDX + f] = (a < 2) ? __ldg(v1_g + f) : __ldg(v2_g + f);
    }
    __syncthreads();

    const float4* b1p = (const float4*)B1 + lane;
    const uint4*  b2p = (const uint4*)B2h + lane;
    int rbuf = 0;

    for (int t = 0; t < 3; t++) {
        const int wofs = t * 4096, bofs = t * 64;

        // Xl = X@Wx+bx (Wx packed in B1 scratch)
        pack_w(Wx_g + wofs, B1, tid);
        if (tid < 64) {
            bias_s[tid]      = __ldg(bf1_g + bofs + tid);
            bias_s[64 + tid] = __ldg(bf2_g + bofs + tid);
        }
        __syncthreads();
        gemm2<0>(X, LDX, B1, bx_g + bofs, Xl, LDA, tid);
        __syncthreads();

        // filter weights -> fragment-major layouts
        stage_b1(Wf1_g + wofs, B1, tid);
        stage_b2(Wf2_g + wofs, B2h, tid);
        __syncthreads();

        // ---- 16 tiles x 4 atoms; warp owns 16 pair-rows of its atom ----
        for (int tt = 0; tt < 16; tt++) {
            const int ia = 4 * tt + rb;

            // rows this lane covers
            const int m0 = 16 * wm + g, m1 = m0 + 8;
            const int j0 = m0 + (m0 >= ia);
            const bool pad = (m1 == 63);
            int j1 = m1 + (m1 >= ia);
            if (pad) j1 = 63;

            // rbf directly into A-fragment registers
            float r0[16], r1[16];
            {
                float px = pos[3 * ia], py = pos[3 * ia + 1], pz = pos[3 * ia + 2];
                float dx = px - pos[3 * j0], dy = py - pos[3 * j0 + 1],
                      dz = pz - pos[3 * j0 + 2];
                float d0 = sqrtf(fmaf(dx, dx, fmaf(dy, dy, dz * dz)));
                dx = px - pos[3 * j1]; dy = py - pos[3 * j1 + 1];
                dz = pz - pos[3 * j1 + 2];
                float d1 = pad ? 1e9f
                               : sqrtf(fmaf(dx, dx, fmaf(dy, dy, dz * dz)));
                float c = (float)tig * 0.15625f;
#pragma unroll
                for (int q = 0; q < 16; q++) {
                    float t0 = d0 - c, t1 = d1 - c;
                    r0[q] = tf32r(ex2f(t0 * t0 * -14.4269504f));
                    r1[q] = tf32r(ex2f(t1 * t1 * -14.4269504f));
                    c += 0.625f;
                }
            }

            // GEMM1 (tf32) with fused epi1 -> h (fp16x2 regs)
            u32 h[8][2];
#pragma unroll
            for (int nb = 0; nb < 8; nb++) {
                float4 f0 = b1p[(nb * 4 + 0) * 32];
                float4 f1 = b1p[(nb * 4 + 1) * 32];
                float4 f2 = b1p[(nb * 4 + 2) * 32];
                float4 f3 = b1p[(nb * 4 + 3) * 32];
                float Bf[16];
                *(float4*)&Bf[0]  = f0; *(float4*)&Bf[4]  = f1;
                *(float4*)&Bf[8]  = f2; *(float4*)&Bf[12] = f3;
                float dd[4] = {0.f, 0.f, 0.f, 0.f};
#pragma unroll
                for (int s = 0; s < 8; s++)
                    mma_tf32(dd, r0[2 * s], r1[2 * s], r0[2 * s + 1],
                             r1[2 * s + 1], Bf[2 * s], Bf[2 * s + 1]);
                float2 bb = *(const float2*)&bias_s[8 * nb + 2 * tig];
                float2 t01 = tanh2(dd[0] + bb.x, dd[1] + bb.y);
                float2 t23 = tanh2(dd[2] + bb.x, dd[3] + bb.y);
                h[nb][0] = packh2(t01.x, t01.y);
                h[nb][1] = packh2(t23.x, t23.y);
            }

            // GEMM2 (fp16) + epi2 fused
            const int j_g  = j0;
            const int j_g8 = m1 + (m1 >= ia);
            float pr[8][2];
#pragma unroll
            for (int nb2 = 0; nb2 < 8; nb2++) {
                uint4 w0 = b2p[(nb2 * 2 + 0) * 32];
                uint4 w1 = b2p[(nb2 * 2 + 1) * 32];
                float d2[4] = {0.f, 0.f, 0.f, 0.f};
                mma_f16(d2, h[0][0], h[0][1], h[1][0], h[1][1], w0.x, w0.y);
                mma_f16(d2, h[2][0], h[2][1], h[3][0], h[3][1], w0.z, w0.w);
                mma_f16(d2, h[4][0], h[4][1], h[5][0], h[5][1], w1.x, w1.y);
                mma_f16(d2, h[6][0], h[6][1], h[7][0], h[7][1], w1.z, w1.w);
                float2 bb = *(const float2*)&bias_s[64 + 8 * nb2 + 2 * tig];
                float2 tg  = tanh2(d2[0] + bb.x, d2[1] + bb.y);
                float2 tg8 = tanh2(d2[2] + bb.x, d2[3] + bb.y);
                float2 xg  = *(const float2*)&Xl[j_g * LDA + 8 * nb2 + 2 * tig];
                float2 xg8 = pad ? make_float2(0.f, 0.f)
                                 : *(const float2*)&Xl[j_g8 * LDA + 8 * nb2 + 2 * tig];
                pr[nb2][0] = fmaf(tg.x, xg.x, tg8.x * xg8.x);
                pr[nb2][1] = fmaf(tg.y, xg.y, tg8.y * xg8.y);
            }
#pragma unroll
            for (int mk = 4; mk <= 16; mk <<= 1) {
#pragma unroll
                for (int nb2 = 0; nb2 < 8; nb2++) {
                    pr[nb2][0] += __shfl_xor_sync(0xffffffffu, pr[nb2][0], mk);
                    pr[nb2][1] += __shfl_xor_sync(0xffffffffu, pr[nb2][1], mk);
                }
            }
            if (g == 0) {
                float* rp = red + (rbuf * 16 + wid) * 64 + 2 * tig;
#pragma unroll
                for (int nb2 = 0; nb2 < 8; nb2++)
                    *(float2*)(rp + 8 * nb2) = make_float2(pr[nb2][0], pr[nb2][1]);
            }
            BAR_RB(rb + 1);
            if (rb_tid < 64) {
                const float* rp = red + (rbuf * 16 + rb * 4) * 64 + rb_tid;
                vs[ia * LDX + rb_tid] = rp[0] + rp[64] + rp[128] + rp[192];
            }
            rbuf ^= 1;
        }
        __syncthreads();

        // v = tanh(vs@Wv1+b); X += v@Wv2+b
        // scratch: Wv1 packed -> B1, Wv2 packed -> B2+red (contiguous 4096),
        // tmpV -> Xl region (Xl dead until next interaction recomputes it)
        pack_w(Wv1_g + wofs, B1, tid);
        pack_w(Wv2_g + wofs, sm + OFF_B2, tid);
        __syncthreads();
        gemm2<1>(vs, LDX, B1, bv1_g + bofs, Xl, LDX, tid);
        __syncthreads();
        gemm2<2>(Xl, LDX, sm + OFF_B2, bv2_g + bofs, X, LDX, tid);
        __syncthreads();
    }

    // ---- output head ----
    {
        float* Wah  = B1;
        float* Wbh  = sm + OFF_B2;
        float* redh = red;
#pragma unroll
        for (int ii = 0; ii < 4; ii++)
            Wah[tid + 512 * ii] = __ldg(W1_g + tid + 512 * ii);
        if (tid < 32) {
            Wbh[tid]      = __ldg(W2_g + tid);
            Wbh[32 + tid] = __ldg(b1_g + tid);
        }
        if (tid == 0) Wbh[64] = __ldg(b2_g);
        __syncthreads();

        int a = tid >> 3, cq = (tid & 7) * 4;
        float acc0 = Wbh[32 + cq + 0], acc1 = Wbh[32 + cq + 1];
        float acc2 = Wbh[32 + cq + 2], acc3 = Wbh[32 + cq + 3];
#pragma unroll 8
        for (int k = 0; k < 64; k++) {
            float xa = X[a * LDX + k];
            const float* wr = Wah + k * 32 + cq;
            acc0 = fmaf(xa, wr[0], acc0);
            acc1 = fmaf(xa, wr[1], acc1);
            acc2 = fmaf(xa, wr[2], acc2);
            acc3 = fmaf(xa, wr[3], acc3);
        }
        float s = fast_tanh(acc0) * Wbh[cq + 0] + fast_tanh(acc1) * Wbh[cq + 1] +
                  fast_tanh(acc2) * Wbh[cq + 2] + fast_tanh(acc3) * Wbh[cq + 3];
#pragma unroll
        for (int off = 16; off > 0; off >>= 1)
            s += __shfl_xor_sync(0xffffffffu, s, off);
        if (lane == 0) redh[wid] = s;
        __syncthreads();
        if (tid == 0) {
            float tot = 0.0f;
#pragma unroll
            for (int w = 0; w < 16; w++) tot += redh[w];
            out_g[b] = tot + 64.0f * Wbh[64];
        }
    }
}

extern "C" void kernel_launch(void* const* d_in, const int* in_sizes, int n_in,
                              void* d_out, int out_size) {
    const float* r_g   = (const float*)d_in[0];
    const float* v1_g  = (const float*)d_in[1];
    const float* v2_g  = (const float*)d_in[2];
    const float* cen_g = (const float*)d_in[3];
    const float* Wx_g  = (const float*)d_in[4];
    const float* bx_g  = (const float*)d_in[5];
    const float* Wf1_g = (const float*)d_in[6];
    const float* bf1_g = (const float*)d_in[7];
    const float* Wf2_g = (const float*)d_in[8];
    const float* bf2_g = (const float*)d_in[9];
    const float* Wv1_g = (const float*)d_in[10];
    const float* bv1_g = (const float*)d_in[11];
    const float* Wv2_g = (const float*)d_in[12];
    const float* bv2_g = (const float*)d_in[13];
    const float* W1_g  = (const float*)d_in[14];
    const float* b1_g  = (const float*)d_in[15];
    const float* W2_g  = (const float*)d_in[16];
    const float* b2_g  = (const float*)d_in[17];
    float* out = (float*)d_out;
    int batch = in_sizes[0] / 192;

    cudaFuncSetAttribute(schnet_kernel,
                         cudaFuncAttributeMaxDynamicSharedMemorySize, SMEM_BYTES);
    schnet_kernel<<<batch, 512, SMEM_BYTES>>>(
        r_g, v1_g, v2_g, cen_g, Wx_g, bx_g, Wf1_g, bf1_g, Wf2_g, bf2_g,
        Wv1_g, bv1_g, Wv2_g, bv2_g, W1_g, b1_g, W2_g, b2_g, out);
}

// round 10
// speedup vs baseline: 1.6287x; 1.0582x over previous
#include <cuda_runtime.h>
#include <cuda_fp16.h>
#include <cstdint>

// ---------------------------------------------------------------------------
// SchNet fused kernel, round 10: both filter GEMMs fp16 m16n8k16.
// rbf packed straight into fp16x2 A-fragments (16 regs), frag-major fp16 B
// for both GEMMs, per-nb2 immediate reduce. 512 thr, 1 CTA/batch.
// ---------------------------------------------------------------------------

typedef unsigned long long u64;
typedef unsigned int u32;

#define LDA 72   // float stride: Xl
#define LDX 68   // X / vs / tmpV stride (scalar path)

// float offsets
#define OFF_POS   0        // 256
#define OFF_BIAS  256      // 128
#define OFF_XL    384      // 64*72 = 4608
#define OFF_X     4992     // 4352
#define OFF_VS    9344     // 4352
#define OFF_B1    13696    // 2048 (fp16 frag-major Wf1)
#define OFF_B2    15744    // 2048 (fp16 frag-major Wf2)
#define OFF_RED   17792    // 2048
#define OFF_SCR   19840    // 4096 (scalar packed-weight scratch)
#define SMEM_FLOATS 23936
#define SMEM_BYTES  (SMEM_FLOATS * 4)   // 95744

#define BAR_RB(id) asm volatile("bar.sync %0, 128;" :: "r"(id) : "memory")

__device__ __forceinline__ float fast_tanh(float x) {
    float e = __expf(2.0f * x);
    return 1.0f - __fdividef(2.0f, e + 1.0f);
}
__device__ __forceinline__ float2 tanh2(float a, float b) {
    float ya = fminf(a * 2.885390082f, 57.7f);
    float yb = fminf(b * 2.885390082f, 57.7f);
    float ta, tb, rp;
    asm("ex2.approx.f32 %0, %1;" : "=f"(ta) : "f"(ya));
    asm("ex2.approx.f32 %0, %1;" : "=f"(tb) : "f"(yb));
    float pa = ta + 1.0f, pb = tb + 1.0f;
    asm("rcp.approx.f32 %0, %1;" : "=f"(rp) : "f"(pa * pb));
    return make_float2(fmaf(-2.0f * pb, rp, 1.0f), fmaf(-2.0f * pa, rp, 1.0f));
}
__device__ __forceinline__ float ex2f(float y) {
    float r; asm("ex2.approx.f32 %0, %1;" : "=f"(r) : "f"(y)); return r;
}
__device__ __forceinline__ u32 packh2(float lo, float hi) {
    __half2 h = __floats2half2_rn(lo, hi);
    return *reinterpret_cast<u32*>(&h);
}
__device__ __forceinline__ void mma_f16(float (&d)[4], u32 a0, u32 a1, u32 a2,
                                        u32 a3, u32 b0, u32 b1) {
    asm("mma.sync.aligned.m16n8k16.row.col.f32.f16.f16.f32 "
        "{%0,%1,%2,%3}, {%4,%5,%6,%7}, {%8,%9}, {%0,%1,%2,%3};"
        : "+f"(d[0]), "+f"(d[1]), "+f"(d[2]), "+f"(d[3])
        : "r"(a0), "r"(a1), "r"(a2), "r"(a3), "r"(b0), "r"(b1));
}

// W[k][n] (64x64 row-major) -> fp16 frag-major:
// half at [(((n>>3)*2 + (i>>2))*32 + 4*(n&7)+((k>>1)&3))*4 + (i&3)]*2 + (k&1),
// i = k>>3.  (identical to round-8/9 proven GEMM2 staging)
__device__ __forceinline__ void stage_bh(const float* __restrict__ g,
                                         __half* __restrict__ s, int tid) {
#pragma unroll
    for (int ii = 0; ii < 8; ii++) {
        int idx = tid + ii * 512;
        int k = idx >> 6, n = idx & 63;
        int ln = 4 * (n & 7) + ((k >> 1) & 3);
        int i = k >> 3;
        s[((((n >> 3) * 2 + (i >> 2)) * 32 + ln) * 4 + (i & 3)) * 2 + (k & 1)] =
            __float2half(__ldg(g + idx));
    }
}

// ---- scalar FFMA2 machinery for small 64x64 GEMMs ----
__device__ __forceinline__ void ffma2(u64& d, u64 a, u64 b) {
    asm("fma.rn.f32x2 %0, %1, %2, %0;" : "+l"(d) : "l"(a), "l"(b));
}
__device__ __forceinline__ void unpack2(u64 v, float& lo, float& hi) {
    asm("mov.b64 {%0, %1}, %2;" : "=f"(lo), "=f"(hi) : "l"(v));
}
__device__ __forceinline__ void pack_w(const float* __restrict__ g,
                                       float* __restrict__ s, int tid) {
#pragma unroll
    for (int ii = 0; ii < 8; ii++) {
        int idx = tid + ii * 512;
        int k = idx >> 6, c = idx & 63;
        int p = c >> 1, cl = c & 1;
        int pos = (p & ~3) | (((p & 3) + ((p >> 3) & 3)) & 3);
        s[(k >> 1) * 128 + pos * 4 + cl * 2 + (k & 1)] = __ldg(g + idx);
    }
}
template <int EPI>
__device__ __forceinline__ void gemm2(const float* __restrict__ A, int lda,
                                      const float* __restrict__ Wp,
                                      const float* __restrict__ bias,
                                      float* __restrict__ C, int ldc, int tid) {
    const int rg = tid >> 3, cg = tid & 7, c0 = cg << 3, x = (cg >> 1) & 3;
    const int u0 = (4 * cg + ((0 + x) & 3)) << 2;
    const int u1 = (4 * cg + ((1 + x) & 3)) << 2;
    const int u2 = (4 * cg + ((2 + x) & 3)) << 2;
    const int u3 = (4 * cg + ((3 + x) & 3)) << 2;
    const float* arow = A + rg * lda;
    u64 acc[8];
#pragma unroll
    for (int c = 0; c < 8; c++) acc[c] = 0ULL;
    const float* wk = Wp;
#pragma unroll 8
    for (int k2 = 0; k2 < 32; k2++) {
        ulonglong2 v0 = *(const ulonglong2*)(wk + u0);
        ulonglong2 v1 = *(const ulonglong2*)(wk + u1);
        ulonglong2 v2 = *(const ulonglong2*)(wk + u2);
        ulonglong2 v3 = *(const ulonglong2*)(wk + u3);
        u64 av = *(const u64*)(arow + 2 * k2);
        ffma2(acc[0], av, v0.x); ffma2(acc[1], av, v0.y);
        ffma2(acc[2], av, v1.x); ffma2(acc[3], av, v1.y);
        ffma2(acc[4], av, v2.x); ffma2(acc[5], av, v2.y);
        ffma2(acc[6], av, v3.x); ffma2(acc[7], av, v3.y);
        wk += 128;
    }
    const float4* bp = (const float4*)(bias + c0);
    float4 bA = __ldg(bp), bB = __ldg(bp + 1);
    float b8[8] = {bA.x, bA.y, bA.z, bA.w, bB.x, bB.y, bB.z, bB.w};
    float* cp = C + rg * ldc + c0;
    float o[8];
#pragma unroll
    for (int c = 0; c < 8; c++) {
        float lo, hi; unpack2(acc[c], lo, hi);
        float v = lo + hi + b8[c];
        if (EPI == 1) v = fast_tanh(v);
        o[c] = v;
    }
    if (EPI == 2) {
        float4 e0 = *(float4*)cp, e1 = *(float4*)(cp + 4);
        o[0] += e0.x; o[1] += e0.y; o[2] += e0.z; o[3] += e0.w;
        o[4] += e1.x; o[5] += e1.y; o[6] += e1.z; o[7] += e1.w;
    }
    *(float4*)cp       = make_float4(o[0], o[1], o[2], o[3]);
    *(float4*)(cp + 4) = make_float4(o[4], o[5], o[6], o[7]);
}

__global__ void __launch_bounds__(512, 1)
schnet_kernel(const float* __restrict__ r_g, const float* __restrict__ v1_g,
              const float* __restrict__ v2_g, const float* __restrict__ cen_g,
              const float* __restrict__ Wx_g,  const float* __restrict__ bx_g,
              const float* __restrict__ Wf1_g, const float* __restrict__ bf1_g,
              const float* __restrict__ Wf2_g, const float* __restrict__ bf2_g,
              const float* __restrict__ Wv1_g, const float* __restrict__ bv1_g,
              const float* __restrict__ Wv2_g, const float* __restrict__ bv2_g,
              const float* __restrict__ W1_g,  const float* __restrict__ b1_g,
              const float* __restrict__ W2_g,  const float* __restrict__ b2_g,
              float* __restrict__ out_g) {
    extern __shared__ float sm[];
    float*  pos    = sm + OFF_POS;
    float*  bias_s = sm + OFF_BIAS;
    float*  Xl     = sm + OFF_XL;
    float*  X      = sm + OFF_X;
    float*  vs     = sm + OFF_VS;
    __half* B1h    = (__half*)(sm + OFF_B1);
    __half* B2h    = (__half*)(sm + OFF_B2);
    float*  red    = sm + OFF_RED;
    float*  scr    = sm + OFF_SCR;

    const int tid  = threadIdx.x, b = blockIdx.x;
    const int wid  = tid >> 5, lane = tid & 31;
    const int rb   = wid >> 2;            // atom-group (4 warps)
    const int wm   = wid & 3;             // warp-within-group
    const int g    = lane >> 2, tig = lane & 3;
    const int rb_tid = tid & 127;

    // ---- init ----
    if (tid < 192) pos[tid] = r_g[b * 192 + tid];
#pragma unroll
    for (int ii = 0; ii < 8; ii++) {
        int idx = tid + ii * 512;
        int a = idx >> 6, f = idx & 63;
        X[a * LDX + f] = (a < 2) ? __ldg(v1_g + f) : __ldg(v2_g + f);
    }
    __syncthreads();

    const uint4* b1p = (const uint4*)B1h + lane;
    const uint4* b2p = (const uint4*)B2h + lane;
    int rbuf = 0;

    for (int t = 0; t < 3; t++) {
        const int wofs = t * 4096, bofs = t * 64;

        // Xl = X@Wx+bx (Wx packed in scratch)
        pack_w(Wx_g + wofs, scr, tid);
        if (tid < 64) {
            bias_s[tid]      = __ldg(bf1_g + bofs + tid);
            bias_s[64 + tid] = __ldg(bf2_g + bofs + tid);
        }
        __syncthreads();
        gemm2<0>(X, LDX, scr, bx_g + bofs, Xl, LDA, tid);
        __syncthreads();

        // filter weights -> fp16 fragment-major layouts
        stage_bh(Wf1_g + wofs, B1h, tid);
        stage_bh(Wf2_g + wofs, B2h, tid);
        __syncthreads();

        // ---- 16 tiles x 4 atoms; warp owns 16 pair-rows of its atom ----
        for (int tt = 0; tt < 16; tt++) {
            const int ia = 4 * tt + rb;

            const int m0 = 16 * wm + g, m1 = m0 + 8;
            const int j0 = m0 + (m0 >= ia);
            const bool pad = (m1 == 63);
            int j1 = m1 + (m1 >= ia);
            if (pad) j1 = 63;

            // rbf directly into fp16x2 A-fragments
            // ra0[u], ra1[u]: u = 2*kb + hb -> k = {16kb + 8hb + 2tig, +1}
            u32 ra0[8], ra1[8];
            {
                float px = pos[3 * ia], py = pos[3 * ia + 1], pz = pos[3 * ia + 2];
                float dx = px - pos[3 * j0], dy = py - pos[3 * j0 + 1],
                      dz = pz - pos[3 * j0 + 2];
                float d0 = sqrtf(fmaf(dx, dx, fmaf(dy, dy, dz * dz)));
                dx = px - pos[3 * j1]; dy = py - pos[3 * j1 + 1];
                dz = pz - pos[3 * j1 + 2];
                float d1 = pad ? 1e9f
                               : sqrtf(fmaf(dx, dx, fmaf(dy, dy, dz * dz)));
#pragma unroll
                for (int u = 0; u < 8; u++) {
                    int kb = u >> 1, hb = u & 1;
                    float c = (float)(16 * kb + 8 * hb + 2 * tig) * 0.15625f;
                    float t0 = d0 - c, t0b = t0 - 0.15625f;
                    float t1 = d1 - c, t1b = t1 - 0.15625f;
                    ra0[u] = packh2(ex2f(t0 * t0 * -14.4269504f),
                                    ex2f(t0b * t0b * -14.4269504f));
                    ra1[u] = packh2(ex2f(t1 * t1 * -14.4269504f),
                                    ex2f(t1b * t1b * -14.4269504f));
                }
            }

            // GEMM1 (fp16) with fused epi1 -> h (fp16x2 regs)
            u32 h[8][2];
#pragma unroll
            for (int nb = 0; nb < 8; nb++) {
                uint4 w0 = b1p[(nb * 2 + 0) * 32];
                uint4 w1 = b1p[(nb * 2 + 1) * 32];
                float dd[4] = {0.f, 0.f, 0.f, 0.f};
                mma_f16(dd, ra0[0], ra1[0], ra0[1], ra1[1], w0.x, w0.y);
                mma_f16(dd, ra0[2], ra1[2], ra0[3], ra1[3], w0.z, w0.w);
                mma_f16(dd, ra0[4], ra1[4], ra0[5], ra1[5], w1.x, w1.y);
                mma_f16(dd, ra0[6], ra1[6], ra0[7], ra1[7], w1.z, w1.w);
                float2 bb = *(const float2*)&bias_s[8 * nb + 2 * tig];
                float2 t01 = tanh2(dd[0] + bb.x, dd[1] + bb.y);
                float2 t23 = tanh2(dd[2] + bb.x, dd[3] + bb.y);
                h[nb][0] = packh2(t01.x, t01.y);
                h[nb][1] = packh2(t23.x, t23.y);
            }

            // GEMM2 (fp16) + epi2 + immediate reduce per nb2
            const int j_g8 = m1 + (m1 >= ia);
#pragma unroll
            for (int nb2 = 0; nb2 < 8; nb2++) {
                uint4 w0 = b2p[(nb2 * 2 + 0) * 32];
                uint4 w1 = b2p[(nb2 * 2 + 1) * 32];
                float d2[4] = {0.f, 0.f, 0.f, 0.f};
                mma_f16(d2, h[0][0], h[0][1], h[1][0], h[1][1], w0.x, w0.y);
                mma_f16(d2, h[2][0], h[2][1], h[3][0], h[3][1], w0.z, w0.w);
                mma_f16(d2, h[4][0], h[4][1], h[5][0], h[5][1], w1.x, w1.y);
                mma_f16(d2, h[6][0], h[6][1], h[7][0], h[7][1], w1.z, w1.w);
                float2 bb = *(const float2*)&bias_s[64 + 8 * nb2 + 2 * tig];
                float2 tg  = tanh2(d2[0] + bb.x, d2[1] + bb.y);
                float2 tg8 = tanh2(d2[2] + bb.x, d2[3] + bb.y);
                float2 xg  = *(const float2*)&Xl[j0 * LDA + 8 * nb2 + 2 * tig];
                float2 xg8 = pad ? make_float2(0.f, 0.f)
                                 : *(const float2*)&Xl[j_g8 * LDA + 8 * nb2 + 2 * tig];
                float p0 = fmaf(tg.x, xg.x, tg8.x * xg8.x);
                float p1 = fmaf(tg.y, xg.y, tg8.y * xg8.y);
#pragma unroll
                for (int mk = 4; mk <= 16; mk <<= 1) {
                    p0 += __shfl_xor_sync(0xffffffffu, p0, mk);
                    p1 += __shfl_xor_sync(0xffffffffu, p1, mk);
                }
                if (g == 0)
                    *(float2*)&red[(rbuf * 16 + wid) * 64 + 8 * nb2 + 2 * tig] =
                        make_float2(p0, p1);
            }
            BAR_RB(rb + 1);
            if (rb_tid < 64) {
                const float* rp = red + (rbuf * 16 + rb * 4) * 64 + rb_tid;
                vs[ia * LDX + rb_tid] = rp[0] + rp[64] + rp[128] + rp[192];
            }
            rbuf ^= 1;
        }
        __syncthreads();

        // v = tanh(vs@Wv1+b); X += v@Wv2+b
        // Wv1 packed -> scr; Wv2 packed -> B1..B2 (contiguous 4096);
        // tmpV -> Xl region (dead until next interaction)
        pack_w(Wv1_g + wofs, scr, tid);
        pack_w(Wv2_g + wofs, sm + OFF_B1, tid);
        __syncthreads();
        gemm2<1>(vs, LDX, scr, bv1_g + bofs, Xl, LDX, tid);
        __syncthreads();
        gemm2<2>(Xl, LDX, sm + OFF_B1, bv2_g + bofs, X, LDX, tid);
        __syncthreads();
    }

    // ---- output head ----
    {
        float* Wah  = scr;                // 2048
        float* Wbh  = sm + OFF_B1;        // 96
        float* redh = red;
#pragma unroll
        for (int ii = 0; ii < 4; ii++)
            Wah[tid + 512 * ii] = __ldg(W1_g + tid + 512 * ii);
        if (tid < 32) {
            Wbh[tid]      = __ldg(W2_g + tid);
            Wbh[32 + tid] = __ldg(b1_g + tid);
        }
        if (tid == 0) Wbh[64] = __ldg(b2_g);
        __syncthreads();

        int a = tid >> 3, cq = (tid & 7) * 4;
        float acc0 = Wbh[32 + cq + 0], acc1 = Wbh[32 + cq + 1];
        float acc2 = Wbh[32 + cq + 2], acc3 = Wbh[32 + cq + 3];
#pragma unroll 8
        for (int k = 0; k < 64; k++) {
            float xa = X[a * LDX + k];
            const float* wr = Wah + k * 32 + cq;
            acc0 = fmaf(xa, wr[0], acc0);
            acc1 = fmaf(xa, wr[1], acc1);
            acc2 = fmaf(xa, wr[2], acc2);
            acc3 = fmaf(xa, wr[3], acc3);
        }
        float s = fast_tanh(acc0) * Wbh[cq + 0] + fast_tanh(acc1) * Wbh[cq + 1] +
                  fast_tanh(acc2) * Wbh[cq + 2] + fast_tanh(acc3) * Wbh[cq + 3];
#pragma unroll
        for (int off = 16; off > 0; off >>= 1)
            s += __shfl_xor_sync(0xffffffffu, s, off);
        if (lane == 0) redh[wid] = s;
        __syncthreads();
        if (tid == 0) {
            float tot = 0.0f;
#pragma unroll
            for (int w = 0; w < 16; w++) tot += redh[w];
            out_g[b] = tot + 64.0f * Wbh[64];
        }
    }
}

extern "C" void kernel_launch(void* const* d_in, const int* in_sizes, int n_in,
                              void* d_out, int out_size) {
    const float* r_g   = (const float*)d_in[0];
    const float* v1_g  = (const float*)d_in[1];
    const float* v2_g  = (const float*)d_in[2];
    const float* cen_g = (const float*)d_in[3];
    const float* Wx_g  = (const float*)d_in[4];
    const float* bx_g  = (const float*)d_in[5];
    const float* Wf1_g = (const float*)d_in[6];
    const float* bf1_g = (const float*)d_in[7];
    const float* Wf2_g = (const float*)d_in[8];
    const float* bf2_g = (const float*)d_in[9];
    const float* Wv1_g = (const float*)d_in[10];
    const float* bv1_g = (const float*)d_in[11];
    const float* Wv2_g = (const float*)d_in[12];
    const float* bv2_g = (const float*)d_in[13];
    const float* W1_g  = (const float*)d_in[14];
    const float* b1_g  = (const float*)d_in[15];
    const float* W2_g  = (const float*)d_in[16];
    const float* b2_g  = (const float*)d_in[17];
    float* out = (float*)d_out;
    int batch = in_sizes[0] / 192;

    cudaFuncSetAttribute(schnet_kernel,
                         cudaFuncAttributeMaxDynamicSharedMemorySize, SMEM_BYTES);
    schnet_kernel<<<batch, 512, SMEM_BYTES>>>(
        r_g, v1_g, v2_g, cen_g, Wx_g, bx_g, Wf1_g, bf1_g, Wf2_g, bf2_g,
        Wv1_g, bv1_g, Wv2_g, bv2_g, W1_g, b1_g, W2_g, b2_g, out);
}

// round 11
// speedup vs baseline: 2.1986x; 1.3499x over previous
#include <cuda_runtime.h>
#include <cuda_fp16.h>
#include <cstdint>

// ---------------------------------------------------------------------------
// SchNet fused kernel, round 11: round-10 structure + MUFU.TANH
// (tanh.approx.f32) replacing the 3-MUFU tanh2 chains everywhere.
// ---------------------------------------------------------------------------

typedef unsigned long long u64;
typedef unsigned int u32;

#define LDA 72   // float stride: Xl
#define LDX 68   // X / vs / tmpV stride (scalar path)

// float offsets
#define OFF_POS   0        // 256
#define OFF_BIAS  256      // 128
#define OFF_XL    384      // 64*72 = 4608
#define OFF_X     4992     // 4352
#define OFF_VS    9344     // 4352
#define OFF_B1    13696    // 2048 (fp16 frag-major Wf1)
#define OFF_B2    15744    // 2048 (fp16 frag-major Wf2)
#define OFF_RED   17792    // 2048
#define OFF_SCR   19840    // 4096 (scalar packed-weight scratch)
#define SMEM_FLOATS 23936
#define SMEM_BYTES  (SMEM_FLOATS * 4)   // 95744

#define BAR_RB(id) asm volatile("bar.sync %0, 128;" :: "r"(id) : "memory")

__device__ __forceinline__ float tanhf_mufu(float x) {
    float r; asm("tanh.approx.f32 %0, %1;" : "=f"(r) : "f"(x)); return r;
}
__device__ __forceinline__ float ex2f(float y) {
    float r; asm("ex2.approx.f32 %0, %1;" : "=f"(r) : "f"(y)); return r;
}
__device__ __forceinline__ u32 packh2(float lo, float hi) {
    __half2 h = __floats2half2_rn(lo, hi);
    return *reinterpret_cast<u32*>(&h);
}
__device__ __forceinline__ void mma_f16(float (&d)[4], u32 a0, u32 a1, u32 a2,
                                        u32 a3, u32 b0, u32 b1) {
    asm("mma.sync.aligned.m16n8k16.row.col.f32.f16.f16.f32 "
        "{%0,%1,%2,%3}, {%4,%5,%6,%7}, {%8,%9}, {%0,%1,%2,%3};"
        : "+f"(d[0]), "+f"(d[1]), "+f"(d[2]), "+f"(d[3])
        : "r"(a0), "r"(a1), "r"(a2), "r"(a3), "r"(b0), "r"(b1));
}

// W[k][n] (64x64 row-major) -> fp16 frag-major (round-10 proven layout)
__device__ __forceinline__ void stage_bh(const float* __restrict__ g,
                                         __half* __restrict__ s, int tid) {
#pragma unroll
    for (int ii = 0; ii < 8; ii++) {
        int idx = tid + ii * 512;
        int k = idx >> 6, n = idx & 63;
        int ln = 4 * (n & 7) + ((k >> 1) & 3);
        int i = k >> 3;
        s[((((n >> 3) * 2 + (i >> 2)) * 32 + ln) * 4 + (i & 3)) * 2 + (k & 1)] =
            __float2half(__ldg(g + idx));
    }
}

// ---- scalar FFMA2 machinery for small 64x64 GEMMs ----
__device__ __forceinline__ void ffma2(u64& d, u64 a, u64 b) {
    asm("fma.rn.f32x2 %0, %1, %2, %0;" : "+l"(d) : "l"(a), "l"(b));
}
__device__ __forceinline__ void unpack2(u64 v, float& lo, float& hi) {
    asm("mov.b64 {%0, %1}, %2;" : "=f"(lo), "=f"(hi) : "l"(v));
}
__device__ __forceinline__ void pack_w(const float* __restrict__ g,
                                       float* __restrict__ s, int tid) {
#pragma unroll
    for (int ii = 0; ii < 8; ii++) {
        int idx = tid + ii * 512;
        int k = idx >> 6, c = idx & 63;
        int p = c >> 1, cl = c & 1;
        int pos = (p & ~3) | (((p & 3) + ((p >> 3) & 3)) & 3);
        s[(k >> 1) * 128 + pos * 4 + cl * 2 + (k & 1)] = __ldg(g + idx);
    }
}
template <int EPI>
__device__ __forceinline__ void gemm2(const float* __restrict__ A, int lda,
                                      const float* __restrict__ Wp,
                                      const float* __restrict__ bias,
                                      float* __restrict__ C, int ldc, int tid) {
    const int rg = tid >> 3, cg = tid & 7, c0 = cg << 3, x = (cg >> 1) & 3;
    const int u0 = (4 * cg + ((0 + x) & 3)) << 2;
    const int u1 = (4 * cg + ((1 + x) & 3)) << 2;
    const int u2 = (4 * cg + ((2 + x) & 3)) << 2;
    const int u3 = (4 * cg + ((3 + x) & 3)) << 2;
    const float* arow = A + rg * lda;
    u64 acc[8];
#pragma unroll
    for (int c = 0; c < 8; c++) acc[c] = 0ULL;
    const float* wk = Wp;
#pragma unroll 8
    for (int k2 = 0; k2 < 32; k2++) {
        ulonglong2 v0 = *(const ulonglong2*)(wk + u0);
        ulonglong2 v1 = *(const ulonglong2*)(wk + u1);
        ulonglong2 v2 = *(const ulonglong2*)(wk + u2);
        ulonglong2 v3 = *(const ulonglong2*)(wk + u3);
        u64 av = *(const u64*)(arow + 2 * k2);
        ffma2(acc[0], av, v0.x); ffma2(acc[1], av, v0.y);
        ffma2(acc[2], av, v1.x); ffma2(acc[3], av, v1.y);
        ffma2(acc[4], av, v2.x); ffma2(acc[5], av, v2.y);
        ffma2(acc[6], av, v3.x); ffma2(acc[7], av, v3.y);
        wk += 128;
    }
    const float4* bp = (const float4*)(bias + c0);
    float4 bA = __ldg(bp), bB = __ldg(bp + 1);
    float b8[8] = {bA.x, bA.y, bA.z, bA.w, bB.x, bB.y, bB.z, bB.w};
    float* cp = C + rg * ldc + c0;
    float o[8];
#pragma unroll
    for (int c = 0; c < 8; c++) {
        float lo, hi; unpack2(acc[c], lo, hi);
        float v = lo + hi + b8[c];
        if (EPI == 1) v = tanhf_mufu(v);
        o[c] = v;
    }
    if (EPI == 2) {
        float4 e0 = *(float4*)cp, e1 = *(float4*)(cp + 4);
        o[0] += e0.x; o[1] += e0.y; o[2] += e0.z; o[3] += e0.w;
        o[4] += e1.x; o[5] += e1.y; o[6] += e1.z; o[7] += e1.w;
    }
    *(float4*)cp       = make_float4(o[0], o[1], o[2], o[3]);
    *(float4*)(cp + 4) = make_float4(o[4], o[5], o[6], o[7]);
}

__global__ void __launch_bounds__(512, 1)
schnet_kernel(const float* __restrict__ r_g, const float* __restrict__ v1_g,
              const float* __restrict__ v2_g, const float* __restrict__ cen_g,
              const float* __restrict__ Wx_g,  const float* __restrict__ bx_g,
              const float* __restrict__ Wf1_g, const float* __restrict__ bf1_g,
              const float* __restrict__ Wf2_g, const float* __restrict__ bf2_g,
              const float* __restrict__ Wv1_g, const float* __restrict__ bv1_g,
              const float* __restrict__ Wv2_g, const float* __restrict__ bv2_g,
              const float* __restrict__ W1_g,  const float* __restrict__ b1_g,
              const float* __restrict__ W2_g,  const float* __restrict__ b2_g,
              float* __restrict__ out_g) {
    extern __shared__ float sm[];
    float*  pos    = sm + OFF_POS;
    float*  bias_s = sm + OFF_BIAS;
    float*  Xl     = sm + OFF_XL;
    float*  X      = sm + OFF_X;
    float*  vs     = sm + OFF_VS;
    __half* B1h    = (__half*)(sm + OFF_B1);
    __half* B2h    = (__half*)(sm + OFF_B2);
    float*  red    = sm + OFF_RED;
    float*  scr    = sm + OFF_SCR;

    const int tid  = threadIdx.x, b = blockIdx.x;
    const int wid  = tid >> 5, lane = tid & 31;
    const int rb   = wid >> 2;            // atom-group (4 warps)
    const int wm   = wid & 3;             // warp-within-group
    const int g    = lane >> 2, tig = lane & 3;
    const int rb_tid = tid & 127;

    // ---- init ----
    if (tid < 192) pos[tid] = r_g[b * 192 + tid];
#pragma unroll
    for (int ii = 0; ii < 8; ii++) {
        int idx = tid + ii * 512;
        int a = idx >> 6, f = idx & 63;
        X[a * LDX + f] = (a < 2) ? __ldg(v1_g + f) : __ldg(v2_g + f);
    }
    __syncthreads();

    const uint4* b1p = (const uint4*)B1h + lane;
    const uint4* b2p = (const uint4*)B2h + lane;
    int rbuf = 0;

    for (int t = 0; t < 3; t++) {
        const int wofs = t * 4096, bofs = t * 64;

        // Xl = X@Wx+bx (Wx packed in scratch)
        pack_w(Wx_g + wofs, scr, tid);
        if (tid < 64) {
            bias_s[tid]      = __ldg(bf1_g + bofs + tid);
            bias_s[64 + tid] = __ldg(bf2_g + bofs + tid);
        }
        __syncthreads();
        gemm2<0>(X, LDX, scr, bx_g + bofs, Xl, LDA, tid);
        __syncthreads();

        // filter weights -> fp16 fragment-major layouts
        stage_bh(Wf1_g + wofs, B1h, tid);
        stage_bh(Wf2_g + wofs, B2h, tid);
        __syncthreads();

        // ---- 16 tiles x 4 atoms; warp owns 16 pair-rows of its atom ----
        for (int tt = 0; tt < 16; tt++) {
            const int ia = 4 * tt + rb;

            const int m0 = 16 * wm + g, m1 = m0 + 8;
            const int j0 = m0 + (m0 >= ia);
            const bool pad = (m1 == 63);
            int j1 = m1 + (m1 >= ia);
            if (pad) j1 = 63;

            // rbf directly into fp16x2 A-fragments
            u32 ra0[8], ra1[8];
            {
                float px = pos[3 * ia], py = pos[3 * ia + 1], pz = pos[3 * ia + 2];
                float dx = px - pos[3 * j0], dy = py - pos[3 * j0 + 1],
                      dz = pz - pos[3 * j0 + 2];
                float d0 = sqrtf(fmaf(dx, dx, fmaf(dy, dy, dz * dz)));
                dx = px - pos[3 * j1]; dy = py - pos[3 * j1 + 1];
                dz = pz - pos[3 * j1 + 2];
                float d1 = pad ? 1e9f
                               : sqrtf(fmaf(dx, dx, fmaf(dy, dy, dz * dz)));
#pragma unroll
                for (int u = 0; u < 8; u++) {
                    int kb = u >> 1, hb = u & 1;
                    float c = (float)(16 * kb + 8 * hb + 2 * tig) * 0.15625f;
                    float t0 = d0 - c, t0b = t0 - 0.15625f;
                    float t1 = d1 - c, t1b = t1 - 0.15625f;
                    ra0[u] = packh2(ex2f(t0 * t0 * -14.4269504f),
                                    ex2f(t0b * t0b * -14.4269504f));
                    ra1[u] = packh2(ex2f(t1 * t1 * -14.4269504f),
                                    ex2f(t1b * t1b * -14.4269504f));
                }
            }

            // GEMM1 (fp16) with fused epi1 -> h (fp16x2 regs)
            u32 h[8][2];
#pragma unroll
            for (int nb = 0; nb < 8; nb++) {
                uint4 w0 = b1p[(nb * 2 + 0) * 32];
                uint4 w1 = b1p[(nb * 2 + 1) * 32];
                float dd[4] = {0.f, 0.f, 0.f, 0.f};
                mma_f16(dd, ra0[0], ra1[0], ra0[1], ra1[1], w0.x, w0.y);
                mma_f16(dd, ra0[2], ra1[2], ra0[3], ra1[3], w0.z, w0.w);
                mma_f16(dd, ra0[4], ra1[4], ra0[5], ra1[5], w1.x, w1.y);
                mma_f16(dd, ra0[6], ra1[6], ra0[7], ra1[7], w1.z, w1.w);
                float2 bb = *(const float2*)&bias_s[8 * nb + 2 * tig];
                h[nb][0] = packh2(tanhf_mufu(dd[0] + bb.x),
                                  tanhf_mufu(dd[1] + bb.y));
                h[nb][1] = packh2(tanhf_mufu(dd[2] + bb.x),
                                  tanhf_mufu(dd[3] + bb.y));
            }

            // GEMM2 (fp16) + epi2 + immediate reduce per nb2
            const int j_g8 = m1 + (m1 >= ia);
#pragma unroll
            for (int nb2 = 0; nb2 < 8; nb2++) {
                uint4 w0 = b2p[(nb2 * 2 + 0) * 32];
                uint4 w1 = b2p[(nb2 * 2 + 1) * 32];
                float d2[4] = {0.f, 0.f, 0.f, 0.f};
                mma_f16(d2, h[0][0], h[0][1], h[1][0], h[1][1], w0.x, w0.y);
                mma_f16(d2, h[2][0], h[2][1], h[3][0], h[3][1], w0.z, w0.w);
                mma_f16(d2, h[4][0], h[4][1], h[5][0], h[5][1], w1.x, w1.y);
                mma_f16(d2, h[6][0], h[6][1], h[7][0], h[7][1], w1.z, w1.w);
                float2 bb = *(const float2*)&bias_s[64 + 8 * nb2 + 2 * tig];
                float2 xg  = *(const float2*)&Xl[j0 * LDA + 8 * nb2 + 2 * tig];
                float2 xg8 = pad ? make_float2(0.f, 0.f)
                                 : *(const float2*)&Xl[j_g8 * LDA + 8 * nb2 + 2 * tig];
                float p0 = fmaf(tanhf_mufu(d2[0] + bb.x), xg.x,
                                tanhf_mufu(d2[2] + bb.x) * xg8.x);
                float p1 = fmaf(tanhf_mufu(d2[1] + bb.y), xg.y,
                                tanhf_mufu(d2[3] + bb.y) * xg8.y);
#pragma unroll
                for (int mk = 4; mk <= 16; mk <<= 1) {
                    p0 += __shfl_xor_sync(0xffffffffu, p0, mk);
                    p1 += __shfl_xor_sync(0xffffffffu, p1, mk);
                }
                if (g == 0)
                    *(float2*)&red[(rbuf * 16 + wid) * 64 + 8 * nb2 + 2 * tig] =
                        make_float2(p0, p1);
            }
            BAR_RB(rb + 1);
            if (rb_tid < 64) {
                const float* rp = red + (rbuf * 16 + rb * 4) * 64 + rb_tid;
                vs[ia * LDX + rb_tid] = rp[0] + rp[64] + rp[128] + rp[192];
            }
            rbuf ^= 1;
        }
        __syncthreads();

        // v = tanh(vs@Wv1+b); X += v@Wv2+b
        pack_w(Wv1_g + wofs, scr, tid);
        pack_w(Wv2_g + wofs, sm + OFF_B1, tid);
        __syncthreads();
        gemm2<1>(vs, LDX, scr, bv1_g + bofs, Xl, LDX, tid);
        __syncthreads();
        gemm2<2>(Xl, LDX, sm + OFF_B1, bv2_g + bofs, X, LDX, tid);
        __syncthreads();
    }

    // ---- output head ----
    {
        float* Wah  = scr;                // 2048
        float* Wbh  = sm + OFF_B1;        // 96
        float* redh = red;
#pragma unroll
        for (int ii = 0; ii < 4; ii++)
            Wah[tid + 512 * ii] = __ldg(W1_g + tid + 512 * ii);
        if (tid < 32) {
            Wbh[tid]      = __ldg(W2_g + tid);
            Wbh[32 + tid] = __ldg(b1_g + tid);
        }
        if (tid == 0) Wbh[64] = __ldg(b2_g);
        __syncthreads();

        int a = tid >> 3, cq = (tid & 7) * 4;
        float acc0 = Wbh[32 + cq + 0], acc1 = Wbh[32 + cq + 1];
        float acc2 = Wbh[32 + cq + 2], acc3 = Wbh[32 + cq + 3];
#pragma unroll 8
        for (int k = 0; k < 64; k++) {
            float xa = X[a * LDX + k];
            const float* wr = Wah + k * 32 + cq;
            acc0 = fmaf(xa, wr[0], acc0);
            acc1 = fmaf(xa, wr[1], acc1);
            acc2 = fmaf(xa, wr[2], acc2);
            acc3 = fmaf(xa, wr[3], acc3);
        }
        float s = tanhf_mufu(acc0) * Wbh[cq + 0] + tanhf_mufu(acc1) * Wbh[cq + 1] +
                  tanhf_mufu(acc2) * Wbh[cq + 2] + tanhf_mufu(acc3) * Wbh[cq + 3];
#pragma unroll
        for (int off = 16; off > 0; off >>= 1)
            s += __shfl_xor_sync(0xffffffffu, s, off);
        if (lane == 0) redh[wid] = s;
        __syncthreads();
        if (tid == 0) {
            float tot = 0.0f;
#pragma unroll
            for (int w = 0; w < 16; w++) tot += redh[w];
            out_g[b] = tot + 64.0f * Wbh[64];
        }
    }
}

extern "C" void kernel_launch(void* const* d_in, const int* in_sizes, int n_in,
                              void* d_out, int out_size) {
    const float* r_g   = (const float*)d_in[0];
    const float* v1_g  = (const float*)d_in[1];
    const float* v2_g  = (const float*)d_in[2];
    const float* cen_g = (const float*)d_in[3];
    const float* Wx_g  = (const float*)d_in[4];
    const float* bx_g  = (const float*)d_in[5];
    const float* Wf1_g = (const float*)d_in[6];
    const float* bf1_g = (const float*)d_in[7];
    const float* Wf2_g = (const float*)d_in[8];
    const float* bf2_g = (const float*)d_in[9];
    const float* Wv1_g = (const float*)d_in[10];
    const float* bv1_g = (const float*)d_in[11];
    const float* Wv2_g = (const float*)d_in[12];
    const float* bv2_g = (const float*)d_in[13];
    const float* W1_g  = (const float*)d_in[14];
    const float* b1_g  = (const float*)d_in[15];
    const float* W2_g  = (const float*)d_in[16];
    const float* b2_g  = (const float*)d_in[17];
    float* out = (float*)d_out;
    int batch = in_sizes[0] / 192;

    cudaFuncSetAttribute(schnet_kernel,
                         cudaFuncAttributeMaxDynamicSharedMemorySize, SMEM_BYTES);
    schnet_kernel<<<batch, 512, SMEM_BYTES>>>(
        r_g, v1_g, v2_g, cen_g, Wx_g, bx_g, Wf1_g, bf1_g, Wf2_g, bf2_g,
        Wv1_g, bv1_g, Wv2_g, bv2_g, W1_g, b1_g, W2_g, b2_g, out);
}

// round 12
// speedup vs baseline: 2.5221x; 1.1471x over previous
#include <cuda_runtime.h>
#include <cuda_fp16.h>
#include <cstdint>

// ---------------------------------------------------------------------------
// SchNet fused kernel, round 12: 32 rows/warp (2 m16 blocks share B frags,
// halving B LDS traffic) + f16x2 MUFU (ex2/tanh) halving MUFU ops.
// 8-atom tiles, 2 warps per atom, 64-thread pair barriers.
// ---------------------------------------------------------------------------

typedef unsigned long long u64;
typedef unsigned int u32;

#define LDA 72   // float stride: Xl
#define LDX 68   // X / vs / tmpV stride (scalar path)

// float offsets
#define OFF_POS   0        // 256
#define OFF_BIAS  256      // 128
#define OFF_XL    384      // 64*72 = 4608
#define OFF_X     4992     // 4352
#define OFF_VS    9344     // 4352
#define OFF_B1    13696    // 2048 (fp16 frag-major Wf1)
#define OFF_B2    15744    // 2048 (fp16 frag-major Wf2)
#define OFF_RED   17792    // 2048
#define OFF_SCR   19840    // 4096 (scalar packed-weight scratch)
#define SMEM_FLOATS 23936
#define SMEM_BYTES  (SMEM_FLOATS * 4)   // 95744

__device__ __forceinline__ float tanhf_mufu(float x) {
    float r; asm("tanh.approx.f32 %0, %1;" : "=f"(r) : "f"(x)); return r;
}
// pack two f32 -> f16x2 (lo = first arg)
__device__ __forceinline__ u32 cvt_h2(float lo, float hi) {
    u32 r; asm("cvt.rn.f16x2.f32 %0, %1, %2;" : "=r"(r) : "f"(hi), "f"(lo));
    return r;
}
__device__ __forceinline__ u32 tanh_h2(float lo, float hi) {
    u32 p = cvt_h2(lo, hi), r;
    asm("tanh.approx.f16x2 %0, %1;" : "=r"(r) : "r"(p));
    return r;
}
__device__ __forceinline__ u32 ex2_h2(float lo, float hi) {
    u32 p = cvt_h2(lo, hi), r;
    asm("ex2.approx.f16x2 %0, %1;" : "=r"(r) : "r"(p));
    return r;
}
__device__ __forceinline__ float2 h2_f2(u32 v) {
    __half2 h = *reinterpret_cast<__half2*>(&v);
    return __half22float2(h);
}
// rbf pair for centers (k, k+1): exp(-10 (d-c)^2) in fp16x2
__device__ __forceinline__ u32 rbf_h2(float d, float c) {
    float t = d - c, tb = t - 0.15625f;
    return ex2_h2(t * t * -14.4269504f, tb * tb * -14.4269504f);
}
__device__ __forceinline__ void mma_f16(float (&d)[4], u32 a0, u32 a1, u32 a2,
                                        u32 a3, u32 b0, u32 b1) {
    asm("mma.sync.aligned.m16n8k16.row.col.f32.f16.f16.f32 "
        "{%0,%1,%2,%3}, {%4,%5,%6,%7}, {%8,%9}, {%0,%1,%2,%3};"
        : "+f"(d[0]), "+f"(d[1]), "+f"(d[2]), "+f"(d[3])
        : "r"(a0), "r"(a1), "r"(a2), "r"(a3), "r"(b0), "r"(b1));
}

// W[k][n] (64x64 row-major) -> fp16 frag-major (proven layout)
__device__ __forceinline__ void stage_bh(const float* __restrict__ g,
                                         __half* __restrict__ s, int tid) {
#pragma unroll
    for (int ii = 0; ii < 8; ii++) {
        int idx = tid + ii * 512;
        int k = idx >> 6, n = idx & 63;
        int ln = 4 * (n & 7) + ((k >> 1) & 3);
        int i = k >> 3;
        s[((((n >> 3) * 2 + (i >> 2)) * 32 + ln) * 4 + (i & 3)) * 2 + (k & 1)] =
            __float2half(__ldg(g + idx));
    }
}

// ---- scalar FFMA2 machinery for small 64x64 GEMMs ----
__device__ __forceinline__ void ffma2(u64& d, u64 a, u64 b) {
    asm("fma.rn.f32x2 %0, %1, %2, %0;" : "+l"(d) : "l"(a), "l"(b));
}
__device__ __forceinline__ void unpack2(u64 v, float& lo, float& hi) {
    asm("mov.b64 {%0, %1}, %2;" : "=f"(lo), "=f"(hi) : "l"(v));
}
__device__ __forceinline__ void pack_w(const float* __restrict__ g,
                                       float* __restrict__ s, int tid) {
#pragma unroll
    for (int ii = 0; ii < 8; ii++) {
        int idx = tid + ii * 512;
        int k = idx >> 6, c = idx & 63;
        int p = c >> 1, cl = c & 1;
        int pos = (p & ~3) | (((p & 3) + ((p >> 3) & 3)) & 3);
        s[(k >> 1) * 128 + pos * 4 + cl * 2 + (k & 1)] = __ldg(g + idx);
    }
}
template <int EPI>
__device__ __forceinline__ void gemm2(const float* __restrict__ A, int lda,
                                      const float* __restrict__ Wp,
                                      const float* __restrict__ bias,
                                      float* __restrict__ C, int ldc, int tid) {
    const int rg = tid >> 3, cg = tid & 7, c0 = cg << 3, x = (cg >> 1) & 3;
    const int u0 = (4 * cg + ((0 + x) & 3)) << 2;
    const int u1 = (4 * cg + ((1 + x) & 3)) << 2;
    const int u2 = (4 * cg + ((2 + x) & 3)) << 2;
    const int u3 = (4 * cg + ((3 + x) & 3)) << 2;
    const float* arow = A + rg * lda;
    u64 acc[8];
#pragma unroll
    for (int c = 0; c < 8; c++) acc[c] = 0ULL;
    const float* wk = Wp;
#pragma unroll 8
    for (int k2 = 0; k2 < 32; k2++) {
        ulonglong2 v0 = *(const ulonglong2*)(wk + u0);
        ulonglong2 v1 = *(const ulonglong2*)(wk + u1);
        ulonglong2 v2 = *(const ulonglong2*)(wk + u2);
        ulonglong2 v3 = *(const ulonglong2*)(wk + u3);
        u64 av = *(const u64*)(arow + 2 * k2);
        ffma2(acc[0], av, v0.x); ffma2(acc[1], av, v0.y);
        ffma2(acc[2], av, v1.x); ffma2(acc[3], av, v1.y);
        ffma2(acc[4], av, v2.x); ffma2(acc[5], av, v2.y);
        ffma2(acc[6], av, v3.x); ffma2(acc[7], av, v3.y);
        wk += 128;
    }
    const float4* bp = (const float4*)(bias + c0);
    float4 bA = __ldg(bp), bB = __ldg(bp + 1);
    float b8[8] = {bA.x, bA.y, bA.z, bA.w, bB.x, bB.y, bB.z, bB.w};
    float* cp = C + rg * ldc + c0;
    float o[8];
#pragma unroll
    for (int c = 0; c < 8; c++) {
        float lo, hi; unpack2(acc[c], lo, hi);
        float v = lo + hi + b8[c];
        if (EPI == 1) v = tanhf_mufu(v);
        o[c] = v;
    }
    if (EPI == 2) {
        float4 e0 = *(float4*)cp, e1 = *(float4*)(cp + 4);
        o[0] += e0.x; o[1] += e0.y; o[2] += e0.z; o[3] += e0.w;
        o[4] += e1.x; o[5] += e1.y; o[6] += e1.z; o[7] += e1.w;
    }
    *(float4*)cp       = make_float4(o[0], o[1], o[2], o[3]);
    *(float4*)(cp + 4) = make_float4(o[4], o[5], o[6], o[7]);
}

__global__ void __launch_bounds__(512, 1)
schnet_kernel(const float* __restrict__ r_g, const float* __restrict__ v1_g,
              const float* __restrict__ v2_g, const float* __restrict__ cen_g,
              const float* __restrict__ Wx_g,  const float* __restrict__ bx_g,
              const float* __restrict__ Wf1_g, const float* __restrict__ bf1_g,
              const float* __restrict__ Wf2_g, const float* __restrict__ bf2_g,
              const float* __restrict__ Wv1_g, const float* __restrict__ bv1_g,
              const float* __restrict__ Wv2_g, const float* __restrict__ bv2_g,
              const float* __restrict__ W1_g,  const float* __restrict__ b1_g,
              const float* __restrict__ W2_g,  const float* __restrict__ b2_g,
              float* __restrict__ out_g) {
    extern __shared__ float sm[];
    float*  pos    = sm + OFF_POS;
    float*  bias_s = sm + OFF_BIAS;
    float*  Xl     = sm + OFF_XL;
    float*  X      = sm + OFF_X;
    float*  vs     = sm + OFF_VS;
    __half* B1h    = (__half*)(sm + OFF_B1);
    __half* B2h    = (__half*)(sm + OFF_B2);
    float*  red    = sm + OFF_RED;
    float*  scr    = sm + OFF_SCR;

    const int tid  = threadIdx.x, b = blockIdx.x;
    const int wid  = tid >> 5, lane = tid & 31;
    const int pair = wid >> 1;            // atom-within-tile (0..7)
    const int wm2  = wid & 1;             // row-half of atom (0..1)
    const int g    = lane >> 2, tig = lane & 3;

    // ---- init ----
    if (tid < 192) pos[tid] = r_g[b * 192 + tid];
#pragma unroll
    for (int ii = 0; ii < 8; ii++) {
        int idx = tid + ii * 512;
        int a = idx >> 6, f = idx & 63;
        X[a * LDX + f] = (a < 2) ? __ldg(v1_g + f) : __ldg(v2_g + f);
    }
    __syncthreads();

    const uint4* b1p = (const uint4*)B1h + lane;
    const uint4* b2p = (const uint4*)B2h + lane;
    int rbuf = 0;

    // lane's four row positions within the atom's 64 pair-rows
    const int mA0 = 32 * wm2 + g;     // block A, row g
    const int mA1 = mA0 + 8;          // block A, row g+8
    const int mB0 = mA0 + 16;         // block B, row g
    const int mB1 = mA0 + 24;         // block B, row g+8 (can be pad=63)
    const bool pad = (mB1 == 63);

    for (int t = 0; t < 3; t++) {
        const int wofs = t * 4096, bofs = t * 64;

        // Xl = X@Wx+bx
        pack_w(Wx_g + wofs, scr, tid);
        if (tid < 64) {
            bias_s[tid]      = __ldg(bf1_g + bofs + tid);
            bias_s[64 + tid] = __ldg(bf2_g + bofs + tid);
        }
        __syncthreads();
        gemm2<0>(X, LDX, scr, bx_g + bofs, Xl, LDA, tid);
        __syncthreads();

        stage_bh(Wf1_g + wofs, B1h, tid);
        stage_bh(Wf2_g + wofs, B2h, tid);
        __syncthreads();

        // ---- 8 tiles x 8 atoms; warp owns 32 pair-rows of its atom ----
        for (int tt = 0; tt < 8; tt++) {
            const int ia = 8 * tt + pair;

            const int jA0 = mA0 + (mA0 >= ia);
            const int jA1 = mA1 + (mA1 >= ia);
            const int jB0 = mB0 + (mB0 >= ia);
            const int jB1 = pad ? 63 : mB1 + (mB1 >= ia);

            // distances for the 4 rows
            float d0, d1, d2, d3;
            {
                float px = pos[3 * ia], py = pos[3 * ia + 1], pz = pos[3 * ia + 2];
                float dx, dy, dz;
                dx = px - pos[3 * jA0]; dy = py - pos[3 * jA0 + 1]; dz = pz - pos[3 * jA0 + 2];
                d0 = sqrtf(fmaf(dx, dx, fmaf(dy, dy, dz * dz)));
                dx = px - pos[3 * jA1]; dy = py - pos[3 * jA1 + 1]; dz = pz - pos[3 * jA1 + 2];
                d1 = sqrtf(fmaf(dx, dx, fmaf(dy, dy, dz * dz)));
                dx = px - pos[3 * jB0]; dy = py - pos[3 * jB0 + 1]; dz = pz - pos[3 * jB0 + 2];
                d2 = sqrtf(fmaf(dx, dx, fmaf(dy, dy, dz * dz)));
                dx = px - pos[3 * jB1]; dy = py - pos[3 * jB1 + 1]; dz = pz - pos[3 * jB1 + 2];
                d3 = pad ? 1e9f : sqrtf(fmaf(dx, dx, fmaf(dy, dy, dz * dz)));
            }

            // rbf into fp16x2 A-fragments (u = 2*kb+hb -> k = 16kb+8hb+2tig)
            u32 raA0[8], raA1[8], raB0[8], raB1[8];
#pragma unroll
            for (int u = 0; u < 8; u++) {
                int kb = u >> 1, hb = u & 1;
                float c = (float)(16 * kb + 8 * hb + 2 * tig) * 0.15625f;
                raA0[u] = rbf_h2(d0, c);
                raA1[u] = rbf_h2(d1, c);
                raB0[u] = rbf_h2(d2, c);
                raB1[u] = rbf_h2(d3, c);
            }

            // GEMM1 (fp16): both m-blocks share B fragments; fused epi1
            u32 hA[8][2], hB[8][2];
#pragma unroll
            for (int nb = 0; nb < 8; nb++) {
                uint4 w0 = b1p[(nb * 2 + 0) * 32];
                uint4 w1 = b1p[(nb * 2 + 1) * 32];
                float dA[4] = {0.f, 0.f, 0.f, 0.f};
                float dB[4] = {0.f, 0.f, 0.f, 0.f};
                mma_f16(dA, raA0[0], raA1[0], raA0[1], raA1[1], w0.x, w0.y);
                mma_f16(dA, raA0[2], raA1[2], raA0[3], raA1[3], w0.z, w0.w);
                mma_f16(dA, raA0[4], raA1[4], raA0[5], raA1[5], w1.x, w1.y);
                mma_f16(dA, raA0[6], raA1[6], raA0[7], raA1[7], w1.z, w1.w);
                mma_f16(dB, raB0[0], raB1[0], raB0[1], raB1[1], w0.x, w0.y);
                mma_f16(dB, raB0[2], raB1[2], raB0[3], raB1[3], w0.z, w0.w);
                mma_f16(dB, raB0[4], raB1[4], raB0[5], raB1[5], w1.x, w1.y);
                mma_f16(dB, raB0[6], raB1[6], raB0[7], raB1[7], w1.z, w1.w);
                float2 bb = *(const float2*)&bias_s[8 * nb + 2 * tig];
                hA[nb][0] = tanh_h2(dA[0] + bb.x, dA[1] + bb.y);
                hA[nb][1] = tanh_h2(dA[2] + bb.x, dA[3] + bb.y);
                hB[nb][0] = tanh_h2(dB[0] + bb.x, dB[1] + bb.y);
                hB[nb][1] = tanh_h2(dB[2] + bb.x, dB[3] + bb.y);
            }

            // GEMM2 (fp16) + epi2 + immediate reduce per nb2
#pragma unroll
            for (int nb2 = 0; nb2 < 8; nb2++) {
                uint4 w0 = b2p[(nb2 * 2 + 0) * 32];
                uint4 w1 = b2p[(nb2 * 2 + 1) * 32];
                float dA[4] = {0.f, 0.f, 0.f, 0.f};
                float dB[4] = {0.f, 0.f, 0.f, 0.f};
                mma_f16(dA, hA[0][0], hA[0][1], hA[1][0], hA[1][1], w0.x, w0.y);
                mma_f16(dA, hA[2][0], hA[2][1], hA[3][0], hA[3][1], w0.z, w0.w);
                mma_f16(dA, hA[4][0], hA[4][1], hA[5][0], hA[5][1], w1.x, w1.y);
                mma_f16(dA, hA[6][0], hA[6][1], hA[7][0], hA[7][1], w1.z, w1.w);
                mma_f16(dB, hB[0][0], hB[0][1], hB[1][0], hB[1][1], w0.x, w0.y);
                mma_f16(dB, hB[2][0], hB[2][1], hB[3][0], hB[3][1], w0.z, w0.w);
                mma_f16(dB, hB[4][0], hB[4][1], hB[5][0], hB[5][1], w1.x, w1.y);
                mma_f16(dB, hB[6][0], hB[6][1], hB[7][0], hB[7][1], w1.z, w1.w);

                float2 bb = *(const float2*)&bias_s[64 + 8 * nb2 + 2 * tig];
                float2 fA0 = h2_f2(tanh_h2(dA[0] + bb.x, dA[1] + bb.y));
                float2 fA1 = h2_f2(tanh_h2(dA[2] + bb.x, dA[3] + bb.y));
                float2 fB0 = h2_f2(tanh_h2(dB[0] + bb.x, dB[1] + bb.y));
                float2 fB1 = h2_f2(tanh_h2(dB[2] + bb.x, dB[3] + bb.y));

                const int co = 8 * nb2 + 2 * tig;
                float2 xA0 = *(const float2*)&Xl[jA0 * LDA + co];
                float2 xA1 = *(const float2*)&Xl[jA1 * LDA + co];
                float2 xB0 = *(const float2*)&Xl[jB0 * LDA + co];
                float2 xB1 = pad ? make_float2(0.f, 0.f)
                                 : *(const float2*)&Xl[jB1 * LDA + co];

                float p0 = fmaf(fA0.x, xA0.x, fmaf(fA1.x, xA1.x,
                           fmaf(fB0.x, xB0.x, fB1.x * xB1.x)));
                float p1 = fmaf(fA0.y, xA0.y, fmaf(fA1.y, xA1.y,
                           fmaf(fB0.y, xB0.y, fB1.y * xB1.y)));
#pragma unroll
                for (int mk = 4; mk <= 16; mk <<= 1) {
                    p0 += __shfl_xor_sync(0xffffffffu, p0, mk);
                    p1 += __shfl_xor_sync(0xffffffffu, p1, mk);
                }
                if (g == 0)
                    *(float2*)&red[(rbuf * 16 + wid) * 64 + co] =
                        make_float2(p0, p1);
            }
            asm volatile("bar.sync %0, 64;" :: "r"(1 + pair) : "memory");
            if (wm2 == 0) {
                const float* r0 = red + (rbuf * 16 + wid) * 64;
                const float* r1 = r0 + 64;
                vs[ia * LDX + lane]      = r0[lane] + r1[lane];
                vs[ia * LDX + lane + 32] = r0[lane + 32] + r1[lane + 32];
            }
            rbuf ^= 1;
        }
        __syncthreads();

        // v = tanh(vs@Wv1+b); X += v@Wv2+b
        pack_w(Wv1_g + wofs, scr, tid);
        pack_w(Wv2_g + wofs, sm + OFF_B1, tid);
        __syncthreads();
        gemm2<1>(vs, LDX, scr, bv1_g + bofs, Xl, LDX, tid);
        __syncthreads();
        gemm2<2>(Xl, LDX, sm + OFF_B1, bv2_g + bofs, X, LDX, tid);
        __syncthreads();
    }

    // ---- output head ----
    {
        float* Wah  = scr;
        float* Wbh  = sm + OFF_B1;
        float* redh = red;
#pragma unroll
        for (int ii = 0; ii < 4; ii++)
            Wah[tid + 512 * ii] = __ldg(W1_g + tid + 512 * ii);
        if (tid < 32) {
            Wbh[tid]      = __ldg(W2_g + tid);
            Wbh[32 + tid] = __ldg(b1_g + tid);
        }
        if (tid == 0) Wbh[64] = __ldg(b2_g);
        __syncthreads();

        int a = tid >> 3, cq = (tid & 7) * 4;
        float acc0 = Wbh[32 + cq + 0], acc1 = Wbh[32 + cq + 1];
        float acc2 = Wbh[32 + cq + 2], acc3 = Wbh[32 + cq + 3];
#pragma unroll 8
        for (int k = 0; k < 64; k++) {
            float xa = X[a * LDX + k];
            const float* wr = Wah + k * 32 + cq;
            acc0 = fmaf(xa, wr[0], acc0);
            acc1 = fmaf(xa, wr[1], acc1);
            acc2 = fmaf(xa, wr[2], acc2);
            acc3 = fmaf(xa, wr[3], acc3);
        }
        float s = tanhf_mufu(acc0) * Wbh[cq + 0] + tanhf_mufu(acc1) * Wbh[cq + 1] +
                  tanhf_mufu(acc2) * Wbh[cq + 2] + tanhf_mufu(acc3) * Wbh[cq + 3];
#pragma unroll
        for (int off = 16; off > 0; off >>= 1)
            s += __shfl_xor_sync(0xffffffffu, s, off);
        if (lane == 0) redh[wid] = s;
        __syncthreads();
        if (tid == 0) {
            float tot = 0.0f;
#pragma unroll
            for (int w = 0; w < 16; w++) tot += redh[w];
            out_g[b] = tot + 64.0f * Wbh[64];
        }
    }
}

extern "C" void kernel_launch(void* const* d_in, const int* in_sizes, int n_in,
                              void* d_out, int out_size) {
    const float* r_g   = (const float*)d_in[0];
    const float* v1_g  = (const float*)d_in[1];
    const float* v2_g  = (const float*)d_in[2];
    const float* cen_g = (const float*)d_in[3];
    const float* Wx_g  = (const float*)d_in[4];
    const float* bx_g  = (const float*)d_in[5];
    const float* Wf1_g = (const float*)d_in[6];
    const float* bf1_g = (const float*)d_in[7];
    const float* Wf2_g = (const float*)d_in[8];
    const float* bf2_g = (const float*)d_in[9];
    const float* Wv1_g = (const float*)d_in[10];
    const float* bv1_g = (const float*)d_in[11];
    const float* Wv2_g = (const float*)d_in[12];
    const float* bv2_g = (const float*)d_in[13];
    const float* W1_g  = (const float*)d_in[14];
    const float* b1_g  = (const float*)d_in[15];
    const float* W2_g  = (const float*)d_in[16];
    const float* b2_g  = (const float*)d_in[17];
    float* out = (float*)d_out;
    int batch = in_sizes[0] / 192;

    cudaFuncSetAttribute(schnet_kernel,
                         cudaFuncAttributeMaxDynamicSharedMemorySize, SMEM_BYTES);
    schnet_kernel<<<batch, 512, SMEM_BYTES>>>(
        r_g, v1_g, v2_g, cen_g, Wx_g, bx_g, Wf1_g, bf1_g, Wf2_g, bf2_g,
        Wv1_g, bv1_g, Wv2_g, bv2_g, W1_g, b1_g, W2_g, b2_g, out);
}

// round 13
// speedup vs baseline: 2.8385x; 1.1255x over previous
#include <cuda_runtime.h>
#include <cuda_fp16.h>
#include <cstdint>

// ---------------------------------------------------------------------------
// SchNet fused kernel, round 13: 256 threads / CTA, 2 CTAs per SM.
// Same warp-owns-32-rows fp16 MMA structure as round 12; 4-atom tiles,
// 2 warps per atom. rbf in quadratic FMA form.
// ---------------------------------------------------------------------------

typedef unsigned long long u64;
typedef unsigned int u32;

#define LDA 72   // float stride: Xl
#define LDX 68   // X / vs / tmpV stride (scalar path)

// float offsets
#define OFF_POS   0        // 256
#define OFF_BIAS  256      // 128
#define OFF_XL    384      // 64*72 = 4608
#define OFF_X     4992     // 4352
#define OFF_VS    9344     // 4352
#define OFF_B1    13696    // 2048 (fp16 frag-major Wf1)
#define OFF_B2    15744    // 2048 (fp16 frag-major Wf2)
#define OFF_RED   17792    // 2048
#define OFF_SCR   19840    // 4096 (scalar packed-weight scratch)
#define SMEM_FLOATS 23936
#define SMEM_BYTES  (SMEM_FLOATS * 4)   // 95744 -> 2 CTAs/SM

__device__ __forceinline__ float tanhf_mufu(float x) {
    float r; asm("tanh.approx.f32 %0, %1;" : "=f"(r) : "f"(x)); return r;
}
__device__ __forceinline__ u32 cvt_h2(float lo, float hi) {
    u32 r; asm("cvt.rn.f16x2.f32 %0, %1, %2;" : "=r"(r) : "f"(hi), "f"(lo));
    return r;
}
__device__ __forceinline__ u32 tanh_h2(float lo, float hi) {
    u32 p = cvt_h2(lo, hi), r;
    asm("tanh.approx.f16x2 %0, %1;" : "=r"(r) : "r"(p));
    return r;
}
__device__ __forceinline__ u32 ex2_h2f(float lo, float hi) {
    u32 p = cvt_h2(lo, hi), r;
    asm("ex2.approx.f16x2 %0, %1;" : "=r"(r) : "r"(p));
    return r;
}
__device__ __forceinline__ float2 h2_f2(u32 v) {
    __half2 h = *reinterpret_cast<__half2*>(&v);
    return __half22float2(h);
}
__device__ __forceinline__ void mma_f16(float (&d)[4], u32 a0, u32 a1, u32 a2,
                                        u32 a3, u32 b0, u32 b1) {
    asm("mma.sync.aligned.m16n8k16.row.col.f32.f16.f16.f32 "
        "{%0,%1,%2,%3}, {%4,%5,%6,%7}, {%8,%9}, {%0,%1,%2,%3};"
        : "+f"(d[0]), "+f"(d[1]), "+f"(d[2]), "+f"(d[3])
        : "r"(a0), "r"(a1), "r"(a2), "r"(a3), "r"(b0), "r"(b1));
}

// W[k][n] (64x64 row-major) -> fp16 frag-major (proven layout); 256 threads
__device__ __forceinline__ void stage_bh(const float* __restrict__ g,
                                         __half* __restrict__ s, int tid) {
#pragma unroll
    for (int ii = 0; ii < 16; ii++) {
        int idx = tid + ii * 256;
        int k = idx >> 6, n = idx & 63;
        int ln = 4 * (n & 7) + ((k >> 1) & 3);
        int i = k >> 3;
        s[((((n >> 3) * 2 + (i >> 2)) * 32 + ln) * 4 + (i & 3)) * 2 + (k & 1)] =
            __float2half(__ldg(g + idx));
    }
}

// ---- scalar FFMA2 machinery for small 64x64 GEMMs (2 rows/thread) ----
__device__ __forceinline__ void ffma2(u64& d, u64 a, u64 b) {
    asm("fma.rn.f32x2 %0, %1, %2, %0;" : "+l"(d) : "l"(a), "l"(b));
}
__device__ __forceinline__ void unpack2(u64 v, float& lo, float& hi) {
    asm("mov.b64 {%0, %1}, %2;" : "=f"(lo), "=f"(hi) : "l"(v));
}
__device__ __forceinline__ void pack_w(const float* __restrict__ g,
                                       float* __restrict__ s, int tid) {
#pragma unroll
    for (int ii = 0; ii < 16; ii++) {
        int idx = tid + ii * 256;
        int k = idx >> 6, c = idx & 63;
        int p = c >> 1, cl = c & 1;
        int pos = (p & ~3) | (((p & 3) + ((p >> 3) & 3)) & 3);
        s[(k >> 1) * 128 + pos * 4 + cl * 2 + (k & 1)] = __ldg(g + idx);
    }
}
template <int EPI>
__device__ __forceinline__ void gemm2(const float* __restrict__ A, int lda,
                                      const float* __restrict__ Wp,
                                      const float* __restrict__ bias,
                                      float* __restrict__ C, int ldc, int tid) {
    const int rg = tid >> 3, cg = tid & 7, c0 = cg << 3, x = (cg >> 1) & 3;
    const int u0 = (4 * cg + ((0 + x) & 3)) << 2;
    const int u1 = (4 * cg + ((1 + x) & 3)) << 2;
    const int u2 = (4 * cg + ((2 + x) & 3)) << 2;
    const int u3 = (4 * cg + ((3 + x) & 3)) << 2;
    const float* arow0 = A + rg * lda;
    const float* arow1 = arow0 + 32 * lda;
    u64 acc[2][8];
#pragma unroll
    for (int r = 0; r < 2; r++)
#pragma unroll
        for (int c = 0; c < 8; c++) acc[r][c] = 0ULL;
    const float* wk = Wp;
#pragma unroll 8
    for (int k2 = 0; k2 < 32; k2++) {
        ulonglong2 v0 = *(const ulonglong2*)(wk + u0);
        ulonglong2 v1 = *(const ulonglong2*)(wk + u1);
        ulonglong2 v2 = *(const ulonglong2*)(wk + u2);
        ulonglong2 v3 = *(const ulonglong2*)(wk + u3);
        u64 av0 = *(const u64*)(arow0 + 2 * k2);
        u64 av1 = *(const u64*)(arow1 + 2 * k2);
        ffma2(acc[0][0], av0, v0.x); ffma2(acc[0][1], av0, v0.y);
        ffma2(acc[0][2], av0, v1.x); ffma2(acc[0][3], av0, v1.y);
        ffma2(acc[0][4], av0, v2.x); ffma2(acc[0][5], av0, v2.y);
        ffma2(acc[0][6], av0, v3.x); ffma2(acc[0][7], av0, v3.y);
        ffma2(acc[1][0], av1, v0.x); ffma2(acc[1][1], av1, v0.y);
        ffma2(acc[1][2], av1, v1.x); ffma2(acc[1][3], av1, v1.y);
        ffma2(acc[1][4], av1, v2.x); ffma2(acc[1][5], av1, v2.y);
        ffma2(acc[1][6], av1, v3.x); ffma2(acc[1][7], av1, v3.y);
        wk += 128;
    }
    const float4* bp = (const float4*)(bias + c0);
    float4 bA = __ldg(bp), bB = __ldg(bp + 1);
    float b8[8] = {bA.x, bA.y, bA.z, bA.w, bB.x, bB.y, bB.z, bB.w};
#pragma unroll
    for (int r = 0; r < 2; r++) {
        float* cp = C + (rg + 32 * r) * ldc + c0;
        float o[8];
#pragma unroll
        for (int c = 0; c < 8; c++) {
            float lo, hi; unpack2(acc[r][c], lo, hi);
            float v = lo + hi + b8[c];
            if (EPI == 1) v = tanhf_mufu(v);
            o[c] = v;
        }
        if (EPI == 2) {
            float4 e0 = *(float4*)cp, e1 = *(float4*)(cp + 4);
            o[0] += e0.x; o[1] += e0.y; o[2] += e0.z; o[3] += e0.w;
            o[4] += e1.x; o[5] += e1.y; o[6] += e1.z; o[7] += e1.w;
        }
        *(float4*)cp       = make_float4(o[0], o[1], o[2], o[3]);
        *(float4*)(cp + 4) = make_float4(o[4], o[5], o[6], o[7]);
    }
}

__global__ void __launch_bounds__(256, 2)
schnet_kernel(const float* __restrict__ r_g, const float* __restrict__ v1_g,
              const float* __restrict__ v2_g, const float* __restrict__ cen_g,
              const float* __restrict__ Wx_g,  const float* __restrict__ bx_g,
              const float* __restrict__ Wf1_g, const float* __restrict__ bf1_g,
              const float* __restrict__ Wf2_g, const float* __restrict__ bf2_g,
              const float* __restrict__ Wv1_g, const float* __restrict__ bv1_g,
              const float* __restrict__ Wv2_g, const float* __restrict__ bv2_g,
              const float* __restrict__ W1_g,  const float* __restrict__ b1_g,
              const float* __restrict__ W2_g,  const float* __restrict__ b2_g,
              float* __restrict__ out_g) {
    extern __shared__ float sm[];
    float*  pos    = sm + OFF_POS;
    float*  bias_s = sm + OFF_BIAS;
    float*  Xl     = sm + OFF_XL;
    float*  X      = sm + OFF_X;
    float*  vs     = sm + OFF_VS;
    __half* B1h    = (__half*)(sm + OFF_B1);
    __half* B2h    = (__half*)(sm + OFF_B2);
    float*  red    = sm + OFF_RED;
    float*  scr    = sm + OFF_SCR;

    const int tid  = threadIdx.x, b = blockIdx.x;
    const int wid  = tid >> 5, lane = tid & 31;
    const int pair = wid >> 1;            // atom-within-tile (0..3)
    const int wm2  = wid & 1;             // row-half of atom
    const int g    = lane >> 2, tig = lane & 3;

    // ---- init ----
    if (tid < 192) pos[tid] = r_g[b * 192 + tid];
#pragma unroll
    for (int ii = 0; ii < 16; ii++) {
        int idx = tid + ii * 256;
        int a = idx >> 6, f = idx & 63;
        X[a * LDX + f] = (a < 2) ? __ldg(v1_g + f) : __ldg(v2_g + f);
    }
    __syncthreads();

    const uint4* b1p = (const uint4*)B1h + lane;
    const uint4* b2p = (const uint4*)B2h + lane;
    int rbuf = 0;

    // lane's four row positions within the atom's 64 pair-rows
    const int mA0 = 32 * wm2 + g;
    const int mA1 = mA0 + 8;
    const int mB0 = mA0 + 16;
    const int mB1 = mA0 + 24;             // can be pad=63
    const bool pad = (mB1 == 63);

    for (int t = 0; t < 3; t++) {
        const int wofs = t * 4096, bofs = t * 64;

        // Xl = X@Wx+bx
        pack_w(Wx_g + wofs, scr, tid);
        if (tid < 64) {
            bias_s[tid]      = __ldg(bf1_g + bofs + tid);
            bias_s[64 + tid] = __ldg(bf2_g + bofs + tid);
        }
        __syncthreads();
        gemm2<0>(X, LDX, scr, bx_g + bofs, Xl, LDA, tid);
        __syncthreads();

        stage_bh(Wf1_g + wofs, B1h, tid);
        stage_bh(Wf2_g + wofs, B2h, tid);
        __syncthreads();

        // ---- 16 tiles x 4 atoms; warp owns 32 pair-rows of its atom ----
        for (int tt = 0; tt < 16; tt++) {
            const int ia = 4 * tt + pair;

            const int jA0 = mA0 + (mA0 >= ia);
            const int jA1 = mA1 + (mA1 >= ia);
            const int jB0 = mB0 + (mB0 >= ia);
            const int jB1 = pad ? 63 : mB1 + (mB1 >= ia);

            // distances + quadratic coefficients (y = A + c*(B + C*c))
            float A0, B0, A1, B1c, A2, B2c, A3, B3;
            {
                float px = pos[3 * ia], py = pos[3 * ia + 1], pz = pos[3 * ia + 2];
                float dx, dy, dz, d;
                dx = px - pos[3 * jA0]; dy = py - pos[3 * jA0 + 1]; dz = pz - pos[3 * jA0 + 2];
                d = sqrtf(fmaf(dx, dx, fmaf(dy, dy, dz * dz)));
                A0 = -14.4269504f * d * d; B0 = 28.8539008f * d;
                dx = px - pos[3 * jA1]; dy = py - pos[3 * jA1 + 1]; dz = pz - pos[3 * jA1 + 2];
                d = sqrtf(fmaf(dx, dx, fmaf(dy, dy, dz * dz)));
                A1 = -14.4269504f * d * d; B1c = 28.8539008f * d;
                dx = px - pos[3 * jB0]; dy = py - pos[3 * jB0 + 1]; dz = pz - pos[3 * jB0 + 2];
                d = sqrtf(fmaf(dx, dx, fmaf(dy, dy, dz * dz)));
                A2 = -14.4269504f * d * d; B2c = 28.8539008f * d;
                dx = px - pos[3 * jB1]; dy = py - pos[3 * jB1 + 1]; dz = pz - pos[3 * jB1 + 2];
                d = pad ? 1e9f : sqrtf(fmaf(dx, dx, fmaf(dy, dy, dz * dz)));
                A3 = -14.4269504f * d * d; B3 = 28.8539008f * d;
            }

            // rbf into fp16x2 A-fragments (u = 2*kb+hb -> k = 16kb+8hb+2tig)
            u32 raA0[8], raA1[8], raB0[8], raB1[8];
#pragma unroll
            for (int u = 0; u < 8; u++) {
                int kb = u >> 1, hb = u & 1;
                float c  = (float)(16 * kb + 8 * hb + 2 * tig) * 0.15625f;
                float cb = c + 0.15625f;
                raA0[u] = ex2_h2f(fmaf(c, fmaf(c, -14.4269504f, B0), A0),
                                  fmaf(cb, fmaf(cb, -14.4269504f, B0), A0));
                raA1[u] = ex2_h2f(fmaf(c, fmaf(c, -14.4269504f, B1c), A1),
                                  fmaf(cb, fmaf(cb, -14.4269504f, B1c), A1));
                raB0[u] = ex2_h2f(fmaf(c, fmaf(c, -14.4269504f, B2c), A2),
                                  fmaf(cb, fmaf(cb, -14.4269504f, B2c), A2));
                raB1[u] = ex2_h2f(fmaf(c, fmaf(c, -14.4269504f, B3), A3),
                                  fmaf(cb, fmaf(cb, -14.4269504f, B3), A3));
            }

            // GEMM1 (fp16): both m-blocks share B fragments; fused epi1
            u32 hA[8][2], hB[8][2];
#pragma unroll
            for (int nb = 0; nb < 8; nb++) {
                uint4 w0 = b1p[(nb * 2 + 0) * 32];
                uint4 w1 = b1p[(nb * 2 + 1) * 32];
                float dA[4] = {0.f, 0.f, 0.f, 0.f};
                float dB[4] = {0.f, 0.f, 0.f, 0.f};
                mma_f16(dA, raA0[0], raA1[0], raA0[1], raA1[1], w0.x, w0.y);
                mma_f16(dA, raA0[2], raA1[2], raA0[3], raA1[3], w0.z, w0.w);
                mma_f16(dA, raA0[4], raA1[4], raA0[5], raA1[5], w1.x, w1.y);
                mma_f16(dA, raA0[6], raA1[6], raA0[7], raA1[7], w1.z, w1.w);
                mma_f16(dB, raB0[0], raB1[0], raB0[1], raB1[1], w0.x, w0.y);
                mma_f16(dB, raB0[2], raB1[2], raB0[3], raB1[3], w0.z, w0.w);
                mma_f16(dB, raB0[4], raB1[4], raB0[5], raB1[5], w1.x, w1.y);
                mma_f16(dB, raB0[6], raB1[6], raB0[7], raB1[7], w1.z, w1.w);
                float2 bb = *(const float2*)&bias_s[8 * nb + 2 * tig];
                hA[nb][0] = tanh_h2(dA[0] + bb.x, dA[1] + bb.y);
                hA[nb][1] = tanh_h2(dA[2] + bb.x, dA[3] + bb.y);
                hB[nb][0] = tanh_h2(dB[0] + bb.x, dB[1] + bb.y);
                hB[nb][1] = tanh_h2(dB[2] + bb.x, dB[3] + bb.y);
            }

            // GEMM2 (fp16) + epi2 + immediate reduce per nb2
#pragma unroll
            for (int nb2 = 0; nb2 < 8; nb2++) {
                uint4 w0 = b2p[(nb2 * 2 + 0) * 32];
                uint4 w1 = b2p[(nb2 * 2 + 1) * 32];
                float dA[4] = {0.f, 0.f, 0.f, 0.f};
                float dB[4] = {0.f, 0.f, 0.f, 0.f};
                mma_f16(dA, hA[0][0], hA[0][1], hA[1][0], hA[1][1], w0.x, w0.y);
                mma_f16(dA, hA[2][0], hA[2][1], hA[3][0], hA[3][1], w0.z, w0.w);
                mma_f16(dA, hA[4][0], hA[4][1], hA[5][0], hA[5][1], w1.x, w1.y);
                mma_f16(dA, hA[6][0], hA[6][1], hA[7][0], hA[7][1], w1.z, w1.w);
                mma_f16(dB, hB[0][0], hB[0][1], hB[1][0], hB[1][1], w0.x, w0.y);
                mma_f16(dB, hB[2][0], hB[2][1], hB[3][0], hB[3][1], w0.z, w0.w);
                mma_f16(dB, hB[4][0], hB[4][1], hB[5][0], hB[5][1], w1.x, w1.y);
                mma_f16(dB, hB[6][0], hB[6][1], hB[7][0], hB[7][1], w1.z, w1.w);

                float2 bb = *(const float2*)&bias_s[64 + 8 * nb2 + 2 * tig];
                float2 fA0 = h2_f2(tanh_h2(dA[0] + bb.x, dA[1] + bb.y));
                float2 fA1 = h2_f2(tanh_h2(dA[2] + bb.x, dA[3] + bb.y));
                float2 fB0 = h2_f2(tanh_h2(dB[0] + bb.x, dB[1] + bb.y));
                float2 fB1 = h2_f2(tanh_h2(dB[2] + bb.x, dB[3] + bb.y));

                const int co = 8 * nb2 + 2 * tig;
                float2 xA0 = *(const float2*)&Xl[jA0 * LDA + co];
                float2 xA1 = *(const float2*)&Xl[jA1 * LDA + co];
                float2 xB0 = *(const float2*)&Xl[jB0 * LDA + co];
                float2 xB1 = pad ? make_float2(0.f, 0.f)
                                 : *(const float2*)&Xl[jB1 * LDA + co];

                float p0 = fmaf(fA0.x, xA0.x, fmaf(fA1.x, xA1.x,
                           fmaf(fB0.x, xB0.x, fB1.x * xB1.x)));
                float p1 = fmaf(fA0.y, xA0.y, fmaf(fA1.y, xA1.y,
                           fmaf(fB0.y, xB0.y, fB1.y * xB1.y)));
#pragma unroll
                for (int mk = 4; mk <= 16; mk <<= 1) {
                    p0 += __shfl_xor_sync(0xffffffffu, p0, mk);
                    p1 += __shfl_xor_sync(0xffffffffu, p1, mk);
                }
                if (g == 0)
                    *(float2*)&red[(rbuf * 8 + wid) * 64 + co] =
                        make_float2(p0, p1);
            }
            asm volatile("bar.sync %0, 64;" :: "r"(1 + pair) : "memory");
            if (wm2 == 0) {
                const float* r0 = red + (rbuf * 8 + wid) * 64;
                const float* r1 = r0 + 64;
                vs[ia * LDX + lane]      = r0[lane] + r1[lane];
                vs[ia * LDX + lane + 32] = r0[lane + 32] + r1[lane + 32];
            }
            rbuf ^= 1;
        }
        __syncthreads();

        // v = tanh(vs@Wv1+b); X += v@Wv2+b
        pack_w(Wv1_g + wofs, scr, tid);
        pack_w(Wv2_g + wofs, sm + OFF_B1, tid);
        __syncthreads();
        gemm2<1>(vs, LDX, scr, bv1_g + bofs, Xl, LDX, tid);
        __syncthreads();
        gemm2<2>(Xl, LDX, sm + OFF_B1, bv2_g + bofs, X, LDX, tid);
        __syncthreads();
    }

    // ---- output head ----
    {
        float* Wah  = scr;
        float* Wbh  = sm + OFF_B1;
        float* redh = red;
#pragma unroll
        for (int ii = 0; ii < 8; ii++)
            Wah[tid + 256 * ii] = __ldg(W1_g + tid + 256 * ii);
        if (tid < 32) {
            Wbh[tid]      = __ldg(W2_g + tid);
            Wbh[32 + tid] = __ldg(b1_g + tid);
        }
        if (tid == 0) Wbh[64] = __ldg(b2_g);
        __syncthreads();

        int a = tid >> 2, cq = (tid & 3) * 8;
        float acc[8];
#pragma unroll
        for (int j = 0; j < 8; j++) acc[j] = Wbh[32 + cq + j];
#pragma unroll 8
        for (int k = 0; k < 64; k++) {
            float xa = X[a * LDX + k];
            const float* wr = Wah + k * 32 + cq;
#pragma unroll
            for (int j = 0; j < 8; j++) acc[j] = fmaf(xa, wr[j], acc[j]);
        }
        float s = 0.0f;
#pragma unroll
        for (int j = 0; j < 8; j++)
            s = fmaf(tanhf_mufu(acc[j]), Wbh[cq + j], s);
#pragma unroll
        for (int off = 16; off > 0; off >>= 1)
            s += __shfl_xor_sync(0xffffffffu, s, off);
        if (lane == 0) redh[wid] = s;
        __syncthreads();
        if (tid == 0) {
            float tot = 0.0f;
#pragma unroll
            for (int w = 0; w < 8; w++) tot += redh[w];
            out_g[b] = tot + 64.0f * Wbh[64];
        }
    }
}

extern "C" void kernel_launch(void* const* d_in, const int* in_sizes, int n_in,
                              void* d_out, int out_size) {
    const float* r_g   = (const float*)d_in[0];
    const float* v1_g  = (const float*)d_in[1];
    const float* v2_g  = (const float*)d_in[2];
    const float* cen_g = (const float*)d_in[3];
    const float* Wx_g  = (const float*)d_in[4];
    const float* bx_g  = (const float*)d_in[5];
    const float* Wf1_g = (const float*)d_in[6];
    const float* bf1_g = (const float*)d_in[7];
    const float* Wf2_g = (const float*)d_in[8];
    const float* bf2_g = (const float*)d_in[9];
    const float* Wv1_g = (const float*)d_in[10];
    const float* bv1_g = (const float*)d_in[11];
    const float* Wv2_g = (const float*)d_in[12];
    const float* bv2_g = (const float*)d_in[13];
    const float* W1_g  = (const float*)d_in[14];
    const float* b1_g  = (const float*)d_in[15];
    const float* W2_g  = (const float*)d_in[16];
    const float* b2_g  = (const float*)d_in[17];
    float* out = (float*)d_out;
    int batch = in_sizes[0] / 192;

    cudaFuncSetAttribute(schnet_kernel,
                         cudaFuncAttributeMaxDynamicSharedMemorySize, SMEM_BYTES);
    schnet_kernel<<<batch, 256, SMEM_BYTES>>>(
        r_g, v1_g, v2_g, cen_g, Wx_g, bx_g, Wf1_g, bf1_g, Wf2_g, bf2_g,
        Wv1_g, bv1_g, Wv2_g, bv2_g, W1_g, b1_g, W2_g, b2_g, out);
}